// round 14
// baseline (speedup 1.0000x reference)
#include <cuda_runtime.h>
#include <cuda_bf16.h>
#include <math.h>
#include <cstdint>

#define Bb   4
#define Vv   4096
#define Kk   128
#define Cc   128
#define NBLK 4
#define KP   20
#define HST  68

#define AH_OFF 0
#define AL_OFF (128*KP)
#define BH_OFF (2*128*KP)
#define BL_OFF (3*128*KP)
#define STG_U32 (4*128*KP)
#define MLP_SMEM ((STG_U32 + 2*128*HST) * 4)
#define MC_SMEM (2 * STG_U32 * 4)

// bigmm 64-row tile stage
#define A64H 0
#define A64L (64*KP)
#define B64H (2*64*KP)
#define B64L (2*64*KP + 128*KP)
#define STG64 (2*64*KP + 2*128*KP)

// ---------------- scratch ----------------
__device__ float g_x[Bb*Vv*Cc];
__device__ float g_xdiff[Bb*Vv*Cc];
__device__ float g_gx[Bb*Vv*Cc];
__device__ float g_gy[Bb*Vv*Cc];
__device__ float g_gfeat[Bb*Vv*Cc];
__device__ float g_xspec[Bb*Kk*Cc];
__device__ uint32_t g_evAh[Bb*Vv*64],  g_evAl[Bb*Vv*64];
__device__ uint32_t g_evBh[Bb*128*2048], g_evBl[Bb*128*2048];
__device__ uint32_t g_gxeAh[Bb*Vv*64], g_gxeAl[Bb*Vv*64];
__device__ uint32_t g_gyeAh[Bb*Vv*64], g_gyeAl[Bb*Vv*64];
__device__ uint32_t g_ysh[Bb*128*64],  g_ysl[Bb*128*64];

// ---------------- helpers ----------------
__device__ __forceinline__ uint32_t f2bf2(float e0, float e1) {
    uint32_t r;
    asm("cvt.rn.bf16x2.f32 %0, %1, %2;" : "=r"(r) : "f"(e1), "f"(e0));
    return r;
}
__device__ __forceinline__ float bhi(float v) {
    return __bfloat162float(__float2bfloat16(v));
}
__device__ __forceinline__ void split2(float v0, float v1, uint32_t& h, uint32_t& l) {
    float h0 = bhi(v0), h1 = bhi(v1);
    h = f2bf2(h0, h1);
    l = f2bf2(v0 - h0, v1 - h1);
}

#define MMA_BF16(c, a, b0, b1) \
    asm volatile("mma.sync.aligned.m16n8k16.row.col.f32.bf16.bf16.f32 " \
        "{%0,%1,%2,%3},{%4,%5,%6,%7},{%8,%9},{%0,%1,%2,%3};" \
        : "+f"((c)[0]), "+f"((c)[1]), "+f"((c)[2]), "+f"((c)[3]) \
        : "r"((a)[0]), "r"((a)[1]), "r"((a)[2]), "r"((a)[3]), "r"(b0), "r"(b1))

__device__ __forceinline__ void pfA(float4 av[4], const float* __restrict__ A,
                                    long lda, int kt) {
    int row = threadIdx.x >> 1, kh = (threadIdx.x & 1) * 16;
    const float* ap = A + (long)row * lda + kt * 32 + kh;
    av[0] = *(const float4*)ap;
    av[1] = *(const float4*)(ap + 4);
    av[2] = *(const float4*)(ap + 8);
    av[3] = *(const float4*)(ap + 12);
}
__device__ __forceinline__ void stA(uint32_t* H, uint32_t* L, const float4 av[4]) {
    int row = threadIdx.x >> 1, p0 = (threadIdx.x & 1) * 8;
    uint32_t h[8], l[8];
    #pragma unroll
    for (int q = 0; q < 4; q++) {
        float4 v = av[q];
        float h0 = bhi(v.x), h1 = bhi(v.y), h2 = bhi(v.z), h3 = bhi(v.w);
        h[q*2]   = f2bf2(h0, h1);
        h[q*2+1] = f2bf2(h2, h3);
        l[q*2]   = f2bf2(v.x - h0, v.y - h1);
        l[q*2+1] = f2bf2(v.z - h2, v.w - h3);
    }
    uint4* dh = (uint4*)(H + row * KP + p0);
    dh[0] = make_uint4(h[0], h[1], h[2], h[3]);
    dh[1] = make_uint4(h[4], h[5], h[6], h[7]);
    uint4* dl = (uint4*)(L + row * KP + p0);
    dl[0] = make_uint4(l[0], l[1], l[2], l[3]);
    dl[1] = make_uint4(l[4], l[5], l[6], l[7]);
}
__device__ __forceinline__ void pfB(float bv[16], const float* __restrict__ B, int kt) {
    int n = threadIdx.x & 127, pr = threadIdx.x >> 7;
    #pragma unroll
    for (int i = 0; i < 8; i++) {
        int p = pr * 8 + i;
        bv[2*i]   = B[(long)(kt * 32 + 2 * p) * 128 + n];
        bv[2*i+1] = B[(long)(kt * 32 + 2 * p + 1) * 128 + n];
    }
}
__device__ __forceinline__ void stB(uint32_t* H, uint32_t* L, const float bv[16]) {
    int n = threadIdx.x & 127, pr = threadIdx.x >> 7;
    #pragma unroll
    for (int i = 0; i < 8; i++) {
        int p = pr * 8 + i;
        split2(bv[2*i], bv[2*i+1], H[n*KP + p], L[n*KP + p]);
    }
}
__device__ __forceinline__ void pfPk(uint4 r[4], const uint32_t* __restrict__ GH,
                                     const uint32_t* __restrict__ GL, long ldp, long p0) {
    int row = threadIdx.x >> 1, half = threadIdx.x & 1;
    long off = (long)row * ldp + p0 + half * 8;
    r[0] = *(const uint4*)(GH + off);
    r[1] = *(const uint4*)(GH + off + 4);
    r[2] = *(const uint4*)(GL + off);
    r[3] = *(const uint4*)(GL + off + 4);
}
__device__ __forceinline__ void stPk(uint32_t* H, uint32_t* L, const uint4 r[4]) {
    int row = threadIdx.x >> 1, half = threadIdx.x & 1;
    *(uint4*)(H + row * KP + half * 8)     = r[0];
    *(uint4*)(H + row * KP + half * 8 + 4) = r[1];
    *(uint4*)(L + row * KP + half * 8)     = r[2];
    *(uint4*)(L + row * KP + half * 8 + 4) = r[3];
}

__device__ __forceinline__ void mma_step(const uint32_t* st, int ks, float acc[2][8][4]) {
    int lane = threadIdx.x & 31, g = lane >> 2, t4 = lane & 3;
    int wid = threadIdx.x >> 5;
    int m0 = (wid & 3) * 32, n0 = (wid >> 2) * 64;
    int pb = ks * 8 + t4;
    const uint32_t* AH = st + AH_OFF;
    const uint32_t* AL = st + AL_OFF;
    const uint32_t* BHp = st + BH_OFF;
    const uint32_t* BLp = st + BL_OFF;
    uint32_t ah[2][4], al[2][4];
    #pragma unroll
    for (int mt = 0; mt < 2; mt++) {
        int m = m0 + mt * 16 + g;
        ah[mt][0] = AH[m*KP+pb];     ah[mt][1] = AH[(m+8)*KP+pb];
        ah[mt][2] = AH[m*KP+pb+4];   ah[mt][3] = AH[(m+8)*KP+pb+4];
        al[mt][0] = AL[m*KP+pb];     al[mt][1] = AL[(m+8)*KP+pb];
        al[mt][2] = AL[m*KP+pb+4];   al[mt][3] = AL[(m+8)*KP+pb+4];
    }
    #pragma unroll
    for (int nt = 0; nt < 8; nt++) {
        int n = n0 + nt * 8 + g;
        uint32_t bh0 = BHp[n*KP+pb], bh1 = BHp[n*KP+pb+4];
        uint32_t bl0 = BLp[n*KP+pb], bl1 = BLp[n*KP+pb+4];
        #pragma unroll
        for (int mt = 0; mt < 2; mt++) {
            MMA_BF16(acc[mt][nt], ah[mt], bh0, bh1);
            MMA_BF16(acc[mt][nt], ah[mt], bl0, bl1);
            MMA_BF16(acc[mt][nt], al[mt], bh0, bh1);
        }
    }
}

__device__ __forceinline__ void mma_stepA(const uint32_t* AH, const uint32_t* AL,
                                          int pa0, const uint32_t* BHp, const uint32_t* BLp,
                                          int ks, float acc[2][8][4]) {
    int lane = threadIdx.x & 31, g = lane >> 2, t4 = lane & 3;
    int wid = threadIdx.x >> 5;
    int m0 = (wid & 3) * 32, n0 = (wid >> 2) * 64;
    int pa = pa0 + ks * 8 + t4;
    int pb = ks * 8 + t4;
    uint32_t ah[2][4], al[2][4];
    #pragma unroll
    for (int mt = 0; mt < 2; mt++) {
        int m = m0 + mt * 16 + g;
        ah[mt][0] = AH[m*HST+pa];     ah[mt][1] = AH[(m+8)*HST+pa];
        ah[mt][2] = AH[m*HST+pa+4];   ah[mt][3] = AH[(m+8)*HST+pa+4];
        al[mt][0] = AL[m*HST+pa];     al[mt][1] = AL[(m+8)*HST+pa];
        al[mt][2] = AL[m*HST+pa+4];   al[mt][3] = AL[(m+8)*HST+pa+4];
    }
    #pragma unroll
    for (int nt = 0; nt < 8; nt++) {
        int n = n0 + nt * 8 + g;
        uint32_t bh0 = BHp[n*KP+pb], bh1 = BHp[n*KP+pb+4];
        uint32_t bl0 = BLp[n*KP+pb], bl1 = BLp[n*KP+pb+4];
        #pragma unroll
        for (int mt = 0; mt < 2; mt++) {
            MMA_BF16(acc[mt][nt], ah[mt], bh0, bh1);
            MMA_BF16(acc[mt][nt], ah[mt], bl0, bl1);
            MMA_BF16(acc[mt][nt], al[mt], bh0, bh1);
        }
    }
}

__device__ __forceinline__ void zacc(float acc[2][8][4]) {
    #pragma unroll
    for (int i = 0; i < 2; i++)
        #pragma unroll
        for (int j = 0; j < 8; j++)
            #pragma unroll
            for (int q = 0; q < 4; q++) acc[i][j][q] = 0.0f;
}

__device__ void mma_gemm(uint32_t* sm, const float* __restrict__ A, long lda,
                         const float* __restrict__ B, int K, float acc[2][8][4]) {
    int KT = K / 32;
    {
        float4 av[4]; float bv[16];
        pfA(av, A, lda, 0);
        pfB(bv, B, 0);
        stA(sm + AH_OFF, sm + AL_OFF, av);
        stB(sm + BH_OFF, sm + BL_OFF, bv);
    }
    __syncthreads();
    for (int kt = 0; kt < KT; kt++) {
        float4 av[4]; float bv[16];
        bool has = (kt + 1 < KT);
        if (has) { pfA(av, A, lda, kt + 1); pfB(bv, B, kt + 1); }
        mma_step(sm, 0, acc);
        mma_step(sm, 1, acc);
        __syncthreads();
        if (has) {
            stA(sm + AH_OFF, sm + AL_OFF, av);
            stB(sm + BH_OFF, sm + BL_OFF, bv);
        }
        __syncthreads();
    }
}

__device__ void smemA_gemm(const uint32_t* AH, const uint32_t* AL, uint32_t* stage,
                           const float* __restrict__ B, float acc[2][8][4]) {
    {
        float bv[16];
        pfB(bv, B, 0);
        stB(stage + BH_OFF, stage + BL_OFF, bv);
    }
    __syncthreads();
    for (int kt = 0; kt < 4; kt++) {
        float bv[16];
        bool has = (kt < 3);
        if (has) pfB(bv, B, kt + 1);
        mma_stepA(AH, AL, kt * 16, stage + BH_OFF, stage + BL_OFF, 0, acc);
        mma_stepA(AH, AL, kt * 16, stage + BH_OFF, stage + BL_OFF, 1, acc);
        __syncthreads();
        if (has) stB(stage + BH_OFF, stage + BL_OFF, bv);
        __syncthreads();
    }
}

// ---------------- bigmm 64-row helpers ----------------
__device__ __forceinline__ void pfA64(float4 av[2], const float* __restrict__ A,
                                      long lda, int kt) {
    int row = threadIdx.x >> 2, kh = (threadIdx.x & 3) * 8;
    const float* ap = A + (long)row * lda + kt * 32 + kh;
    av[0] = *(const float4*)ap;
    av[1] = *(const float4*)(ap + 4);
}
__device__ __forceinline__ void stA64(uint32_t* H, uint32_t* L, const float4 av[2]) {
    int row = threadIdx.x >> 2, p0 = (threadIdx.x & 3) * 4;
    uint32_t h[4], l[4];
    #pragma unroll
    for (int q = 0; q < 2; q++) {
        float4 v = av[q];
        float h0 = bhi(v.x), h1 = bhi(v.y), h2 = bhi(v.z), h3 = bhi(v.w);
        h[q*2]   = f2bf2(h0, h1);
        h[q*2+1] = f2bf2(h2, h3);
        l[q*2]   = f2bf2(v.x - h0, v.y - h1);
        l[q*2+1] = f2bf2(v.z - h2, v.w - h3);
    }
    *(uint4*)(H + row * KP + p0) = make_uint4(h[0], h[1], h[2], h[3]);
    *(uint4*)(L + row * KP + p0) = make_uint4(l[0], l[1], l[2], l[3]);
}

__device__ __forceinline__ void mma_step64(const uint32_t* st, int ks, float acc[2][4][4]) {
    int lane = threadIdx.x & 31, g = lane >> 2, t4 = lane & 3;
    int wid = threadIdx.x >> 5;
    int m0 = (wid & 1) * 32, n0 = (wid >> 1) * 32;
    int pb = ks * 8 + t4;
    const uint32_t* AH = st + A64H;
    const uint32_t* AL = st + A64L;
    const uint32_t* BHp = st + B64H;
    const uint32_t* BLp = st + B64L;
    uint32_t ah[2][4], al[2][4];
    #pragma unroll
    for (int mt = 0; mt < 2; mt++) {
        int m = m0 + mt * 16 + g;
        ah[mt][0] = AH[m*KP+pb];     ah[mt][1] = AH[(m+8)*KP+pb];
        ah[mt][2] = AH[m*KP+pb+4];   ah[mt][3] = AH[(m+8)*KP+pb+4];
        al[mt][0] = AL[m*KP+pb];     al[mt][1] = AL[(m+8)*KP+pb];
        al[mt][2] = AL[m*KP+pb+4];   al[mt][3] = AL[(m+8)*KP+pb+4];
    }
    #pragma unroll
    for (int nt = 0; nt < 4; nt++) {
        int n = n0 + nt * 8 + g;
        uint32_t bh0 = BHp[n*KP+pb], bh1 = BHp[n*KP+pb+4];
        uint32_t bl0 = BLp[n*KP+pb], bl1 = BLp[n*KP+pb+4];
        #pragma unroll
        for (int mt = 0; mt < 2; mt++) {
            MMA_BF16(acc[mt][nt], ah[mt], bh0, bh1);
            MMA_BF16(acc[mt][nt], ah[mt], bl0, bl1);
            MMA_BF16(acc[mt][nt], al[mt], bh0, bh1);
        }
    }
}

// ---------------- pack kernels ----------------
__global__ __launch_bounds__(256) void k_packEvA(const float* __restrict__ evecs) {
    int gid = blockIdx.x * 256 + threadIdx.x;
    float2 v = ((const float2*)evecs)[gid];
    split2(v.x, v.y, g_evAh[gid], g_evAl[gid]);
}
__global__ __launch_bounds__(256) void k_packEvB(const float* __restrict__ evecs) {
    int b = blockIdx.y;
    int e = blockIdx.x * 256 + threadIdx.x;
    int p = e & 2047, n = e >> 11;
    const float* src = evecs + (long)b * Vv * 128;
    float v0 = src[(long)(2 * p) * 128 + n];
    float v1 = src[(long)(2 * p + 1) * 128 + n];
    long o = ((long)b * 128 + n) * 2048 + p;
    split2(v0, v1, g_evBh[o], g_evBl[o]);
}
__global__ __launch_bounds__(256) void k_input(const float* __restrict__ xin,
                                               const float* __restrict__ Wf,
                                               const float* __restrict__ bf) {
    int gid = blockIdx.x * 256 + threadIdx.x;
    int r = gid >> 7, c = gid & 127;
    float s = bf[c];
    #pragma unroll
    for (int k = 0; k < 16; k++) s += xin[r * 16 + k] * Wf[k * 128 + c];
    g_x[gid] = s;
}

// ---------------- big GEMM: BM=64, 2 CTAs/SM ----------------
__global__ __launch_bounds__(256) void k_bigmm(const float* __restrict__ gradX,
                                               const float* __restrict__ gradY) {
    __shared__ uint32_t sm[STG64];
    int b = blockIdx.y, z = blockIdx.z;
    int row0 = blockIdx.x * 64;
    const float* A = (z ? gradY : gradX) + (long)b * Vv * Vv + (long)row0 * Vv;
    const uint32_t* BH = g_evBh + (long)b * 128 * 2048;
    const uint32_t* BL = g_evBl + (long)b * 128 * 2048;
    float acc[2][4][4];
    #pragma unroll
    for (int i = 0; i < 2; i++)
        #pragma unroll
        for (int j = 0; j < 4; j++)
            #pragma unroll
            for (int q = 0; q < 4; q++) acc[i][j][q] = 0.0f;
    {
        float4 av[2]; uint4 pv[4];
        pfA64(av, A, Vv, 0);
        pfPk(pv, BH, BL, 2048, 0);
        stA64(sm + A64H, sm + A64L, av);
        stPk(sm + B64H, sm + B64L, pv);
    }
    __syncthreads();
    for (int kt = 0; kt < 128; kt++) {
        float4 av[2]; uint4 pv[4];
        bool has = (kt < 127);
        if (has) {
            pfA64(av, A, Vv, kt + 1);
            pfPk(pv, BH, BL, 2048, (long)(kt + 1) * 16);
        }
        mma_step64(sm, 0, acc);
        mma_step64(sm, 1, acc);
        __syncthreads();
        if (has) {
            stA64(sm + A64H, sm + A64L, av);
            stPk(sm + B64H, sm + B64L, pv);
        }
        __syncthreads();
    }
    uint32_t* DH = (z ? g_gyeAh : g_gxeAh) + (long)b * Vv * 64;
    uint32_t* DL = (z ? g_gyeAl : g_gxeAl) + (long)b * Vv * 64;
    int lane = threadIdx.x & 31, g = lane >> 2, t4 = lane & 3;
    int wid = threadIdx.x >> 5;
    int m0 = (wid & 1) * 32, n0 = (wid >> 1) * 32;
    #pragma unroll
    for (int mt = 0; mt < 2; mt++)
        #pragma unroll
        for (int nt = 0; nt < 4; nt++) {
            int cp = (n0 + nt * 8 + t4 * 2) >> 1;
            long r = row0 + m0 + mt * 16 + g;
            split2(acc[mt][nt][0], acc[mt][nt][1], DH[r * 64 + cp], DL[r * 64 + cp]);
            split2(acc[mt][nt][2], acc[mt][nt][3], DH[(r + 8) * 64 + cp], DL[(r + 8) * 64 + cp]);
        }
}

// ---------------- spectral ----------------
__global__ __launch_bounds__(256) void k_zero_spec() {
    g_xspec[blockIdx.x * 256 + threadIdx.x] = 0.0f;
}

__global__ __launch_bounds__(256) void k_spec(const float* __restrict__ mass) {
    __shared__ uint32_t sm[STG_U32];
    int b = blockIdx.y;
    int v0 = blockIdx.x * 128;
    float acc[2][8][4]; zacc(acc);
    int n = threadIdx.x & 127;
    int pr = threadIdx.x >> 7;
    const uint32_t* AH = g_evBh + (long)b * 128 * 2048;
    const uint32_t* AL = g_evBl + (long)b * 128 * 2048;
    for (int kt = 0; kt < 4; kt++) {
        __syncthreads();
        uint4 pv[4];
        pfPk(pv, AH, AL, 2048, (long)(v0 >> 1) + kt * 16);
        stPk(sm + AH_OFF, sm + AL_OFF, pv);
        #pragma unroll
        for (int i = 0; i < 8; i++) {
            int p = pr * 8 + i;
            long v = (long)(b * Vv + v0 + kt * 32 + 2 * p);
            float v0f = g_x[v * 128 + n] * mass[v];
            float v1f = g_x[(v + 1) * 128 + n] * mass[v + 1];
            split2(v0f, v1f, sm[BH_OFF + n*KP + p], sm[BL_OFF + n*KP + p]);
        }
        __syncthreads();
        mma_step(sm, 0, acc);
        mma_step(sm, 1, acc);
    }
    int lane = threadIdx.x & 31, g = lane >> 2, t4 = lane & 3;
    int wid = threadIdx.x >> 5;
    int m0 = (wid & 3) * 32, n0 = (wid >> 2) * 64;
    float* outb = g_xspec + b * Kk * Cc;
    #pragma unroll
    for (int mt = 0; mt < 2; mt++)
        #pragma unroll
        for (int nt = 0; nt < 8; nt++) {
            int r = m0 + mt * 16 + g;
            int c = n0 + nt * 8 + t4 * 2;
            atomicAdd(&outb[r * 128 + c],           acc[mt][nt][0]);
            atomicAdd(&outb[r * 128 + c + 1],       acc[mt][nt][1]);
            atomicAdd(&outb[(r + 8) * 128 + c],     acc[mt][nt][2]);
            atomicAdd(&outb[(r + 8) * 128 + c + 1], acc[mt][nt][3]);
        }
}

__global__ __launch_bounds__(256) void k_scale(const float* __restrict__ evals,
                                               const float* __restrict__ tpar, int blk) {
    int gid = blockIdx.x * 256 + threadIdx.x;
    int p = gid & 63;
    int c = (gid >> 6) & 127;
    int b = gid >> 13;
    float ti = fmaxf(tpar[blk * 128 + c], 1e-8f);
    int k0 = 2 * p;
    float v0 = expf(-evals[b * 128 + k0] * ti)     * g_xspec[(b * 128 + k0) * 128 + c];
    float v1 = expf(-evals[b * 128 + k0 + 1] * ti) * g_xspec[(b * 128 + k0 + 1) * 128 + c];
    split2(v0, v1, g_ysh[gid], g_ysl[gid]);
}

// xdiff / gx / gy — pipelined packed copies
__global__ __launch_bounds__(256) void k_fbg() {
    __shared__ uint32_t sm[STG_U32];
    int b = blockIdx.y, z = blockIdx.z;
    int row0 = blockIdx.x * 128;
    long rowg = (long)b * Vv + row0;
    const uint32_t *AH, *AL;
    float* O;
    if (z == 0)      { AH = g_evAh + rowg * 64;  AL = g_evAl + rowg * 64;  O = g_xdiff + (long)b * Vv * Cc; }
    else if (z == 1) { AH = g_gxeAh + rowg * 64; AL = g_gxeAl + rowg * 64; O = g_gx + (long)b * Vv * Cc; }
    else             { AH = g_gyeAh + rowg * 64; AL = g_gyeAl + rowg * 64; O = g_gy + (long)b * Vv * Cc; }
    const uint32_t* BH = g_ysh + (long)b * 128 * 64;
    const uint32_t* BL = g_ysl + (long)b * 128 * 64;
    float acc[2][8][4]; zacc(acc);
    {
        uint4 pa[4], pb_[4];
        pfPk(pa, AH, AL, 64, 0);
        pfPk(pb_, BH, BL, 64, 0);
        stPk(sm + AH_OFF, sm + AL_OFF, pa);
        stPk(sm + BH_OFF, sm + BL_OFF, pb_);
    }
    __syncthreads();
    for (int kt = 0; kt < 4; kt++) {
        uint4 pa[4], pb_[4];
        bool has = (kt < 3);
        if (has) {
            pfPk(pa, AH, AL, 64, (kt + 1) * 16);
            pfPk(pb_, BH, BL, 64, (kt + 1) * 16);
        }
        mma_step(sm, 0, acc);
        mma_step(sm, 1, acc);
        __syncthreads();
        if (has) {
            stPk(sm + AH_OFF, sm + AL_OFF, pa);
            stPk(sm + BH_OFF, sm + BL_OFF, pb_);
        }
        __syncthreads();
    }
    int lane = threadIdx.x & 31, g = lane >> 2, t4 = lane & 3;
    int wid = threadIdx.x >> 5;
    int m0 = (wid & 3) * 32, n0 = (wid >> 2) * 64;
    #pragma unroll
    for (int mt = 0; mt < 2; mt++)
        #pragma unroll
        for (int nt = 0; nt < 8; nt++) {
            int r = row0 + m0 + mt * 16 + g;
            int c = n0 + nt * 8 + t4 * 2;
            *(float2*)(O + (long)r * 128 + c)       = make_float2(acc[mt][nt][0], acc[mt][nt][1]);
            *(float2*)(O + (long)(r + 8) * 128 + c) = make_float2(acc[mt][nt][2], acc[mt][nt][3]);
        }
}

// ---------------- fused complex-linear + tanh ----------------
__global__ __launch_bounds__(256) void k_cplx(const float* __restrict__ Are,
                                              const float* __restrict__ Aim) {
    extern __shared__ uint32_t smc[];
    uint32_t* st0 = smc;
    uint32_t* st1 = smc + STG_U32;
    int b = blockIdx.y;
    long off = (long)b * Vv * Cc;
    int row0 = blockIdx.x * 128;
    int lane = threadIdx.x & 31, g = lane >> 2, t4 = lane & 3;
    int wid = threadIdx.x >> 5;
    int m0 = (wid & 3) * 32, n0 = (wid >> 2) * 64;
    float abr[2][8][4]; zacc(abr);
    float abi[2][8][4]; zacc(abi);
    for (int kt = 0; kt < 4; kt++) {
        __syncthreads();
        {
            float4 av[4]; float bv[16];
            pfA(av, g_gx + off + (long)row0 * Cc, Cc, kt);
            pfB(bv, Are, kt);
            stA(st0 + AH_OFF, st0 + AL_OFF, av);
            stB(st0 + BH_OFF, st0 + BL_OFF, bv);
            pfA(av, g_gy + off + (long)row0 * Cc, Cc, kt);
            pfB(bv, Aim, kt);
            stA(st1 + AH_OFF, st1 + AL_OFF, av);
            stB(st1 + BH_OFF, st1 + BL_OFF, bv);
        }
        __syncthreads();
        #pragma unroll
        for (int ks = 0; ks < 2; ks++) {
            int pb = ks * 8 + t4;
            uint32_t xh[2][4], xl[2][4], yh[2][4], yl[2][4];
            #pragma unroll
            for (int mt = 0; mt < 2; mt++) {
                int m = m0 + mt * 16 + g;
                xh[mt][0] = st0[AH_OFF+m*KP+pb];   xh[mt][1] = st0[AH_OFF+(m+8)*KP+pb];
                xh[mt][2] = st0[AH_OFF+m*KP+pb+4]; xh[mt][3] = st0[AH_OFF+(m+8)*KP+pb+4];
                xl[mt][0] = st0[AL_OFF+m*KP+pb];   xl[mt][1] = st0[AL_OFF+(m+8)*KP+pb];
                xl[mt][2] = st0[AL_OFF+m*KP+pb+4]; xl[mt][3] = st0[AL_OFF+(m+8)*KP+pb+4];
                yh[mt][0] = st1[AH_OFF+m*KP+pb];   yh[mt][1] = st1[AH_OFF+(m+8)*KP+pb];
                yh[mt][2] = st1[AH_OFF+m*KP+pb+4]; yh[mt][3] = st1[AH_OFF+(m+8)*KP+pb+4];
                yl[mt][0] = st1[AL_OFF+m*KP+pb];   yl[mt][1] = st1[AL_OFF+(m+8)*KP+pb];
                yl[mt][2] = st1[AL_OFF+m*KP+pb+4]; yl[mt][3] = st1[AL_OFF+(m+8)*KP+pb+4];
            }
            #pragma unroll
            for (int nt = 0; nt < 8; nt++) {
                int n = n0 + nt * 8 + g;
                uint32_t rh0 = st0[BH_OFF+n*KP+pb], rh1 = st0[BH_OFF+n*KP+pb+4];
                uint32_t rl0 = st0[BL_OFF+n*KP+pb], rl1 = st0[BL_OFF+n*KP+pb+4];
                uint32_t ih0 = st1[BH_OFF+n*KP+pb], ih1 = st1[BH_OFF+n*KP+pb+4];
                uint32_t il0 = st1[BL_OFF+n*KP+pb], il1 = st1[BL_OFF+n*KP+pb+4];
                uint32_t nh0 = ih0 ^ 0x80008000u, nh1 = ih1 ^ 0x80008000u;
                uint32_t nl0 = il0 ^ 0x80008000u, nl1 = il1 ^ 0x80008000u;
                #pragma unroll
                for (int mt = 0; mt < 2; mt++) {
                    MMA_BF16(abr[mt][nt], xh[mt], rh0, rh1);
                    MMA_BF16(abr[mt][nt], xh[mt], rl0, rl1);
                    MMA_BF16(abr[mt][nt], xl[mt], rh0, rh1);
                    MMA_BF16(abr[mt][nt], yh[mt], nh0, nh1);
                    MMA_BF16(abr[mt][nt], yh[mt], nl0, nl1);
                    MMA_BF16(abr[mt][nt], yl[mt], nh0, nh1);
                    MMA_BF16(abi[mt][nt], yh[mt], rh0, rh1);
                    MMA_BF16(abi[mt][nt], yh[mt], rl0, rl1);
                    MMA_BF16(abi[mt][nt], yl[mt], rh0, rh1);
                    MMA_BF16(abi[mt][nt], xh[mt], ih0, ih1);
                    MMA_BF16(abi[mt][nt], xh[mt], il0, il1);
                    MMA_BF16(abi[mt][nt], xl[mt], ih0, ih1);
                }
            }
        }
    }
    #pragma unroll
    for (int mt = 0; mt < 2; mt++)
        #pragma unroll
        for (int nt = 0; nt < 8; nt++) {
            int c = n0 + nt * 8 + t4 * 2;
            #pragma unroll
            for (int h = 0; h < 2; h++) {
                int r = row0 + m0 + mt * 16 + g + h * 8;
                long base = off + (long)r * 128 + c;
                float2 gx2 = *(const float2*)(g_gx + base);
                float2 gy2 = *(const float2*)(g_gy + base);
                float2 o;
                o.x = tanhf(gx2.x * abr[mt][nt][h*2]   + gy2.x * abi[mt][nt][h*2]);
                o.y = tanhf(gx2.y * abr[mt][nt][h*2+1] + gy2.y * abi[mt][nt][h*2+1]);
                *(float2*)(g_gfeat + base) = o;
            }
        }
}

// ---------------- fused 3-layer MLP ----------------
__global__ __launch_bounds__(256) void k_mlp(const float* __restrict__ W0,
                                             const float* __restrict__ b0,
                                             const float* __restrict__ W1,
                                             const float* __restrict__ b1,
                                             const float* __restrict__ W2,
                                             const float* __restrict__ b2) {
    extern __shared__ uint32_t smd[];
    uint32_t* stage = smd;
    uint32_t* hH = smd + STG_U32;
    uint32_t* hL = hH + 128 * HST;
    int row0 = blockIdx.x * 128;
    int lane = threadIdx.x & 31, g = lane >> 2, t4 = lane & 3;
    int wid = threadIdx.x >> 5;
    int m0 = (wid & 3) * 32, n0 = (wid >> 2) * 64;

    float acc[2][8][4]; zacc(acc);
    mma_gemm(stage, g_x     + (long)row0 * Cc, Cc, W0,             Cc, acc);
    mma_gemm(stage, g_xdiff + (long)row0 * Cc, Cc, W0 + 128 * 128, Cc, acc);
    mma_gemm(stage, g_gfeat + (long)row0 * Cc, Cc, W0 + 256 * 128, Cc, acc);

    #pragma unroll
    for (int mt = 0; mt < 2; mt++)
        #pragma unroll
        for (int nt = 0; nt < 8; nt++) {
            int c = n0 + nt * 8 + t4 * 2;
            float2 bb = *(const float2*)(b0 + c);
            int cp = c >> 1;
            int r = m0 + mt * 16 + g;
            split2(fmaxf(acc[mt][nt][0] + bb.x, 0.0f), fmaxf(acc[mt][nt][1] + bb.y, 0.0f),
                   hH[r * HST + cp], hL[r * HST + cp]);
            split2(fmaxf(acc[mt][nt][2] + bb.x, 0.0f), fmaxf(acc[mt][nt][3] + bb.y, 0.0f),
                   hH[(r + 8) * HST + cp], hL[(r + 8) * HST + cp]);
        }
    __syncthreads();

    zacc(acc);
    smemA_gemm(hH, hL, stage, W1, acc);
    __syncthreads();
    #pragma unroll
    for (int mt = 0; mt < 2; mt++)
        #pragma unroll
        for (int nt = 0; nt < 8; nt++) {
            int c = n0 + nt * 8 + t4 * 2;
            float2 bb = *(const float2*)(b1 + c);
            int cp = c >> 1;
            int r = m0 + mt * 16 + g;
            split2(fmaxf(acc[mt][nt][0] + bb.x, 0.0f), fmaxf(acc[mt][nt][1] + bb.y, 0.0f),
                   hH[r * HST + cp], hL[r * HST + cp]);
            split2(fmaxf(acc[mt][nt][2] + bb.x, 0.0f), fmaxf(acc[mt][nt][3] + bb.y, 0.0f),
                   hH[(r + 8) * HST + cp], hL[(r + 8) * HST + cp]);
        }
    __syncthreads();

    zacc(acc);
    smemA_gemm(hH, hL, stage, W2, acc);
    #pragma unroll
    for (int mt = 0; mt < 2; mt++)
        #pragma unroll
        for (int nt = 0; nt < 8; nt++) {
            int c = n0 + nt * 8 + t4 * 2;
            float2 bb = *(const float2*)(b2 + c);
            #pragma unroll
            for (int h = 0; h < 2; h++) {
                int r = row0 + m0 + mt * 16 + g + h * 8;
                float2 xv = *(const float2*)(g_x + (long)r * 128 + c);
                xv.x += acc[mt][nt][h * 2]     + bb.x;
                xv.y += acc[mt][nt][h * 2 + 1] + bb.y;
                *(float2*)(g_x + (long)r * 128 + c) = xv;
            }
        }
}

// ---------------- final linear ----------------
__global__ __launch_bounds__(256) void k_final(const float* __restrict__ Wl,
                                               const float* __restrict__ bl,
                                               float* __restrict__ out) {
    __shared__ uint32_t sm[STG_U32];
    int row0 = blockIdx.x * 128;
    float acc[2][8][4]; zacc(acc);
    mma_gemm(sm, g_x + (long)row0 * Cc, Cc, Wl, Cc, acc);
    int lane = threadIdx.x & 31, g = lane >> 2, t4 = lane & 3;
    int wid = threadIdx.x >> 5;
    int m0 = (wid & 3) * 32, n0 = (wid >> 2) * 64;
    #pragma unroll
    for (int mt = 0; mt < 2; mt++)
        #pragma unroll
        for (int nt = 0; nt < 8; nt++) {
            int c = n0 + nt * 8 + t4 * 2;
            float2 bb = *(const float2*)(bl + c);
            int r = row0 + m0 + mt * 16 + g;
            *(float2*)(out + (long)r * 128 + c) = make_float2(
                acc[mt][nt][0] + bb.x, acc[mt][nt][1] + bb.y);
            *(float2*)(out + (long)(r + 8) * 128 + c) = make_float2(
                acc[mt][nt][2] + bb.x, acc[mt][nt][3] + bb.y);
        }
}

// ---------------- launch ----------------
extern "C" void kernel_launch(void* const* d_in, const int* in_sizes, int n_in,
                              void* d_out, int out_size) {
    const float* x_in  = (const float*)d_in[0];
    const float* mass  = (const float*)d_in[1];
    const float* evals = (const float*)d_in[2];
    const float* evecs = (const float*)d_in[3];
    const float* gradX = (const float*)d_in[4];
    const float* gradY = (const float*)d_in[5];
    const float* Wf    = (const float*)d_in[6];
    const float* bf    = (const float*)d_in[7];
    const float* Wl    = (const float*)d_in[8];
    const float* bl    = (const float*)d_in[9];
    const float* t     = (const float*)d_in[10];
    const float* Are   = (const float*)d_in[11];
    const float* Aim   = (const float*)d_in[12];
    const float* W0    = (const float*)d_in[13];
    const float* b0    = (const float*)d_in[14];
    const float* W1    = (const float*)d_in[15];
    const float* b1    = (const float*)d_in[16];
    const float* W2    = (const float*)d_in[17];
    const float* b2    = (const float*)d_in[18];
    float* out = (float*)d_out;

    static int init_attr = 0;
    if (!init_attr) {
        cudaFuncSetAttribute(k_cplx, cudaFuncAttributeMaxDynamicSharedMemorySize, MC_SMEM);
        cudaFuncSetAttribute(k_mlp,  cudaFuncAttributeMaxDynamicSharedMemorySize, MLP_SMEM);
        init_attr = 1;
    }

    k_input<<<(Bb * Vv * Cc) / 256, 256>>>(x_in, Wf, bf);
    k_packEvA<<<(Bb * Vv * 64) / 256, 256>>>(evecs);
    k_packEvB<<<dim3(1024, Bb), 256>>>(evecs);
    k_bigmm<<<dim3(Vv / 64, Bb, 2), 256>>>(gradX, gradY);

    for (int i = 0; i < NBLK; i++) {
        k_zero_spec<<<(Bb * Kk * Cc) / 256, 256>>>();
        k_spec<<<dim3(Vv / 128, Bb), 256>>>(mass);
        k_scale<<<(Bb * 128 * 64) / 256, 256>>>(evals, t, i);
        k_fbg<<<dim3(Vv / 128, Bb, 3), 256>>>();
        k_cplx<<<dim3(Vv / 128, Bb), 256, MC_SMEM>>>(Are + i * Cc * Cc, Aim + i * Cc * Cc);
        k_mlp<<<(Bb * Vv) / 128, 256, MLP_SMEM>>>(W0 + i * 3 * Cc * Cc, b0 + i * Cc,
                                                  W1 + i * Cc * Cc, b1 + i * Cc,
                                                  W2 + i * Cc * Cc, b2 + i * Cc);
    }

    k_final<<<(Bb * Vv) / 128, 256>>>(Wl, bl, out);
}

// round 15
// speedup vs baseline: 1.1276x; 1.1276x over previous
#include <cuda_runtime.h>
#include <cuda_bf16.h>
#include <math.h>
#include <cstdint>

#define Bb   4
#define Vv   4096
#define Kk   128
#define Cc   128
#define NBLK 4
#define KP   20
#define HST  68

#define AH_OFF 0
#define AL_OFF (128*KP)
#define BH_OFF (2*128*KP)
#define BL_OFF (3*128*KP)
#define STG_U32 (4*128*KP)
#define BSTG    (2*128*KP)
// mlp smem: stage (40KB) + extra B stage (20KB) + h tiles (70KB)
#define MLP_SMEM ((STG_U32 + BSTG + 2*128*HST) * 4)
#define MC_SMEM (2 * STG_U32 * 4)

// ---------------- scratch ----------------
__device__ float g_x[Bb*Vv*Cc];
__device__ float g_xdiff[Bb*Vv*Cc];
__device__ float g_gx[Bb*Vv*Cc];
__device__ float g_gy[Bb*Vv*Cc];
__device__ float g_gfeat[Bb*Vv*Cc];
__device__ float g_xspec[Bb*Kk*Cc];
__device__ uint32_t g_evAh[Bb*Vv*64],  g_evAl[Bb*Vv*64];
__device__ uint32_t g_evBh[Bb*128*2048], g_evBl[Bb*128*2048];
__device__ uint32_t g_gxeAh[Bb*Vv*64], g_gxeAl[Bb*Vv*64];
__device__ uint32_t g_gyeAh[Bb*Vv*64], g_gyeAl[Bb*Vv*64];
__device__ uint32_t g_ysh[Bb*128*64],  g_ysl[Bb*128*64];

// ---------------- helpers ----------------
__device__ __forceinline__ uint32_t f2bf2(float e0, float e1) {
    uint32_t r;
    asm("cvt.rn.bf16x2.f32 %0, %1, %2;" : "=r"(r) : "f"(e1), "f"(e0));
    return r;
}
__device__ __forceinline__ float bhi(float v) {
    return __bfloat162float(__float2bfloat16(v));
}
__device__ __forceinline__ void split2(float v0, float v1, uint32_t& h, uint32_t& l) {
    float h0 = bhi(v0), h1 = bhi(v1);
    h = f2bf2(h0, h1);
    l = f2bf2(v0 - h0, v1 - h1);
}

#define MMA_BF16(c, a, b0, b1) \
    asm volatile("mma.sync.aligned.m16n8k16.row.col.f32.bf16.bf16.f32 " \
        "{%0,%1,%2,%3},{%4,%5,%6,%7},{%8,%9},{%0,%1,%2,%3};" \
        : "+f"((c)[0]), "+f"((c)[1]), "+f"((c)[2]), "+f"((c)[3]) \
        : "r"((a)[0]), "r"((a)[1]), "r"((a)[2]), "r"((a)[3]), "r"(b0), "r"(b1))

__device__ __forceinline__ void pfA(float4 av[4], const float* __restrict__ A,
                                    long lda, int kt) {
    int row = threadIdx.x >> 1, kh = (threadIdx.x & 1) * 16;
    const float* ap = A + (long)row * lda + kt * 32 + kh;
    av[0] = *(const float4*)ap;
    av[1] = *(const float4*)(ap + 4);
    av[2] = *(const float4*)(ap + 8);
    av[3] = *(const float4*)(ap + 12);
}
__device__ __forceinline__ void stA(uint32_t* H, uint32_t* L, const float4 av[4]) {
    int row = threadIdx.x >> 1, p0 = (threadIdx.x & 1) * 8;
    uint32_t h[8], l[8];
    #pragma unroll
    for (int q = 0; q < 4; q++) {
        float4 v = av[q];
        float h0 = bhi(v.x), h1 = bhi(v.y), h2 = bhi(v.z), h3 = bhi(v.w);
        h[q*2]   = f2bf2(h0, h1);
        h[q*2+1] = f2bf2(h2, h3);
        l[q*2]   = f2bf2(v.x - h0, v.y - h1);
        l[q*2+1] = f2bf2(v.z - h2, v.w - h3);
    }
    uint4* dh = (uint4*)(H + row * KP + p0);
    dh[0] = make_uint4(h[0], h[1], h[2], h[3]);
    dh[1] = make_uint4(h[4], h[5], h[6], h[7]);
    uint4* dl = (uint4*)(L + row * KP + p0);
    dl[0] = make_uint4(l[0], l[1], l[2], l[3]);
    dl[1] = make_uint4(l[4], l[5], l[6], l[7]);
}
__device__ __forceinline__ void pfB(float bv[16], const float* __restrict__ B, int kt) {
    int n = threadIdx.x & 127, pr = threadIdx.x >> 7;
    #pragma unroll
    for (int i = 0; i < 8; i++) {
        int p = pr * 8 + i;
        bv[2*i]   = B[(long)(kt * 32 + 2 * p) * 128 + n];
        bv[2*i+1] = B[(long)(kt * 32 + 2 * p + 1) * 128 + n];
    }
}
__device__ __forceinline__ void stB(uint32_t* H, uint32_t* L, const float bv[16]) {
    int n = threadIdx.x & 127, pr = threadIdx.x >> 7;
    #pragma unroll
    for (int i = 0; i < 8; i++) {
        int p = pr * 8 + i;
        split2(bv[2*i], bv[2*i+1], H[n*KP + p], L[n*KP + p]);
    }
}
__device__ __forceinline__ void pfPk(uint4 r[4], const uint32_t* __restrict__ GH,
                                     const uint32_t* __restrict__ GL, long ldp, long p0) {
    int row = threadIdx.x >> 1, half = threadIdx.x & 1;
    long off = (long)row * ldp + p0 + half * 8;
    r[0] = *(const uint4*)(GH + off);
    r[1] = *(const uint4*)(GH + off + 4);
    r[2] = *(const uint4*)(GL + off);
    r[3] = *(const uint4*)(GL + off + 4);
}
__device__ __forceinline__ void stPk(uint32_t* H, uint32_t* L, const uint4 r[4]) {
    int row = threadIdx.x >> 1, half = threadIdx.x & 1;
    *(uint4*)(H + row * KP + half * 8)     = r[0];
    *(uint4*)(H + row * KP + half * 8 + 4) = r[1];
    *(uint4*)(L + row * KP + half * 8)     = r[2];
    *(uint4*)(L + row * KP + half * 8 + 4) = r[3];
}

__device__ __forceinline__ void mma_step(const uint32_t* st, int ks, float acc[2][8][4]) {
    int lane = threadIdx.x & 31, g = lane >> 2, t4 = lane & 3;
    int wid = threadIdx.x >> 5;
    int m0 = (wid & 3) * 32, n0 = (wid >> 2) * 64;
    int pb = ks * 8 + t4;
    const uint32_t* AH = st + AH_OFF;
    const uint32_t* AL = st + AL_OFF;
    const uint32_t* BHp = st + BH_OFF;
    const uint32_t* BLp = st + BL_OFF;
    uint32_t ah[2][4], al[2][4];
    #pragma unroll
    for (int mt = 0; mt < 2; mt++) {
        int m = m0 + mt * 16 + g;
        ah[mt][0] = AH[m*KP+pb];     ah[mt][1] = AH[(m+8)*KP+pb];
        ah[mt][2] = AH[m*KP+pb+4];   ah[mt][3] = AH[(m+8)*KP+pb+4];
        al[mt][0] = AL[m*KP+pb];     al[mt][1] = AL[(m+8)*KP+pb];
        al[mt][2] = AL[m*KP+pb+4];   al[mt][3] = AL[(m+8)*KP+pb+4];
    }
    #pragma unroll
    for (int nt = 0; nt < 8; nt++) {
        int n = n0 + nt * 8 + g;
        uint32_t bh0 = BHp[n*KP+pb], bh1 = BHp[n*KP+pb+4];
        uint32_t bl0 = BLp[n*KP+pb], bl1 = BLp[n*KP+pb+4];
        #pragma unroll
        for (int mt = 0; mt < 2; mt++) {
            MMA_BF16(acc[mt][nt], ah[mt], bh0, bh1);
            MMA_BF16(acc[mt][nt], ah[mt], bl0, bl1);
            MMA_BF16(acc[mt][nt], al[mt], bh0, bh1);
        }
    }
}

// A from h-tile (stride HST), B from a 2*128*KP stage region
__device__ __forceinline__ void mma_stepA(const uint32_t* AH, const uint32_t* AL,
                                          int pa0, const uint32_t* BHp, const uint32_t* BLp,
                                          int ks, float acc[2][8][4]) {
    int lane = threadIdx.x & 31, g = lane >> 2, t4 = lane & 3;
    int wid = threadIdx.x >> 5;
    int m0 = (wid & 3) * 32, n0 = (wid >> 2) * 64;
    int pa = pa0 + ks * 8 + t4;
    int pb = ks * 8 + t4;
    uint32_t ah[2][4], al[2][4];
    #pragma unroll
    for (int mt = 0; mt < 2; mt++) {
        int m = m0 + mt * 16 + g;
        ah[mt][0] = AH[m*HST+pa];     ah[mt][1] = AH[(m+8)*HST+pa];
        ah[mt][2] = AH[m*HST+pa+4];   ah[mt][3] = AH[(m+8)*HST+pa+4];
        al[mt][0] = AL[m*HST+pa];     al[mt][1] = AL[(m+8)*HST+pa];
        al[mt][2] = AL[m*HST+pa+4];   al[mt][3] = AL[(m+8)*HST+pa+4];
    }
    #pragma unroll
    for (int nt = 0; nt < 8; nt++) {
        int n = n0 + nt * 8 + g;
        uint32_t bh0 = BHp[n*KP+pb], bh1 = BHp[n*KP+pb+4];
        uint32_t bl0 = BLp[n*KP+pb], bl1 = BLp[n*KP+pb+4];
        #pragma unroll
        for (int mt = 0; mt < 2; mt++) {
            MMA_BF16(acc[mt][nt], ah[mt], bh0, bh1);
            MMA_BF16(acc[mt][nt], ah[mt], bl0, bl1);
            MMA_BF16(acc[mt][nt], al[mt], bh0, bh1);
        }
    }
}

__device__ __forceinline__ void zacc(float acc[2][8][4]) {
    #pragma unroll
    for (int i = 0; i < 2; i++)
        #pragma unroll
        for (int j = 0; j < 8; j++)
            #pragma unroll
            for (int q = 0; q < 4; q++) acc[i][j][q] = 0.0f;
}

// pipelined fp32xfp32 GEMM accumulate (single stage, register prefetch)
__device__ void mma_gemm(uint32_t* sm, const float* __restrict__ A, long lda,
                         const float* __restrict__ B, int K, float acc[2][8][4]) {
    int KT = K / 32;
    {
        float4 av[4]; float bv[16];
        pfA(av, A, lda, 0);
        pfB(bv, B, 0);
        stA(sm + AH_OFF, sm + AL_OFF, av);
        stB(sm + BH_OFF, sm + BL_OFF, bv);
    }
    __syncthreads();
    for (int kt = 0; kt < KT; kt++) {
        float4 av[4]; float bv[16];
        bool has = (kt + 1 < KT);
        if (has) { pfA(av, A, lda, kt + 1); pfB(bv, B, kt + 1); }
        mma_step(sm, 0, acc);
        mma_step(sm, 1, acc);
        __syncthreads();
        if (has) {
            stA(sm + AH_OFF, sm + AL_OFF, av);
            stB(sm + BH_OFF, sm + BL_OFF, bv);
        }
        __syncthreads();
    }
}

// smem-A GEMM with DOUBLE-BUFFERED B stage: one sync per chunk.
// bst = two B buffers, each 2*128*KP (H then L).
__device__ void smemA_gemm2(const uint32_t* AH, const uint32_t* AL, uint32_t* bst,
                            const float* __restrict__ B, float acc[2][8][4]) {
    {
        float bv[16];
        pfB(bv, B, 0);
        stB(bst, bst + 128 * KP, bv);
    }
    __syncthreads();
    for (int kt = 0; kt < 4; kt++) {
        uint32_t* cur = bst + (kt & 1) * BSTG;
        bool has = (kt < 3);
        if (has) {
            float bv[16];
            pfB(bv, B, kt + 1);
            mma_stepA(AH, AL, kt * 16, cur, cur + 128 * KP, 0, acc);
            mma_stepA(AH, AL, kt * 16, cur, cur + 128 * KP, 1, acc);
            uint32_t* nxt = bst + ((kt + 1) & 1) * BSTG;
            stB(nxt, nxt + 128 * KP, bv);
        } else {
            mma_stepA(AH, AL, kt * 16, cur, cur + 128 * KP, 0, acc);
            mma_stepA(AH, AL, kt * 16, cur, cur + 128 * KP, 1, acc);
        }
        __syncthreads();
    }
}

// ---------------- pack kernels ----------------
__global__ __launch_bounds__(256) void k_packEvA(const float* __restrict__ evecs) {
    int gid = blockIdx.x * 256 + threadIdx.x;
    float2 v = ((const float2*)evecs)[gid];
    split2(v.x, v.y, g_evAh[gid], g_evAl[gid]);
}
__global__ __launch_bounds__(256) void k_packEvB(const float* __restrict__ evecs) {
    int b = blockIdx.y;
    int e = blockIdx.x * 256 + threadIdx.x;
    int p = e & 2047, n = e >> 11;
    const float* src = evecs + (long)b * Vv * 128;
    float v0 = src[(long)(2 * p) * 128 + n];
    float v1 = src[(long)(2 * p + 1) * 128 + n];
    long o = ((long)b * 128 + n) * 2048 + p;
    split2(v0, v1, g_evBh[o], g_evBl[o]);
}
__global__ __launch_bounds__(256) void k_input(const float* __restrict__ xin,
                                               const float* __restrict__ Wf,
                                               const float* __restrict__ bf) {
    int gid = blockIdx.x * 256 + threadIdx.x;
    int r = gid >> 7, c = gid & 127;
    float s = bf[c];
    #pragma unroll
    for (int k = 0; k < 16; k++) s += xin[r * 16 + k] * Wf[k * 128 + c];
    g_x[gid] = s;
}

// ---------------- big GEMM (R7/R11 structure, frozen) ----------------
__global__ __launch_bounds__(256) void k_bigmm(const float* __restrict__ gradX,
                                               const float* __restrict__ gradY) {
    __shared__ uint32_t sm[STG_U32];
    int b = blockIdx.y, z = blockIdx.z;
    int row0 = blockIdx.x * 128;
    const float* A = (z ? gradY : gradX) + (long)b * Vv * Vv + (long)row0 * Vv;
    const uint32_t* BH = g_evBh + (long)b * 128 * 2048;
    const uint32_t* BL = g_evBl + (long)b * 128 * 2048;
    float acc[2][8][4]; zacc(acc);
    {
        float4 av[4]; uint4 pv[4];
        pfA(av, A, Vv, 0);
        pfPk(pv, BH, BL, 2048, 0);
        stA(sm + AH_OFF, sm + AL_OFF, av);
        stPk(sm + BH_OFF, sm + BL_OFF, pv);
    }
    __syncthreads();
    for (int kt = 0; kt < 128; kt++) {
        float4 av[4]; uint4 pv[4];
        bool has = (kt < 127);
        if (has) {
            pfA(av, A, Vv, kt + 1);
            pfPk(pv, BH, BL, 2048, (long)(kt + 1) * 16);
        }
        mma_step(sm, 0, acc);
        mma_step(sm, 1, acc);
        __syncthreads();
        if (has) {
            stA(sm + AH_OFF, sm + AL_OFF, av);
            stPk(sm + BH_OFF, sm + BL_OFF, pv);
        }
        __syncthreads();
    }
    uint32_t* DH = (z ? g_gyeAh : g_gxeAh) + (long)b * Vv * 64;
    uint32_t* DL = (z ? g_gyeAl : g_gxeAl) + (long)b * Vv * 64;
    int lane = threadIdx.x & 31, g = lane >> 2, t4 = lane & 3;
    int wid = threadIdx.x >> 5;
    int m0 = (wid & 3) * 32, n0 = (wid >> 2) * 64;
    #pragma unroll
    for (int mt = 0; mt < 2; mt++)
        #pragma unroll
        for (int nt = 0; nt < 8; nt++) {
            int cp = (n0 + nt * 8 + t4 * 2) >> 1;
            long r = row0 + m0 + mt * 16 + g;
            split2(acc[mt][nt][0], acc[mt][nt][1], DH[r * 64 + cp], DL[r * 64 + cp]);
            split2(acc[mt][nt][2], acc[mt][nt][3], DH[(r + 8) * 64 + cp], DL[(r + 8) * 64 + cp]);
        }
}

// ---------------- spectral ----------------
__global__ __launch_bounds__(256) void k_zero_spec() {
    g_xspec[blockIdx.x * 256 + threadIdx.x] = 0.0f;
}

__global__ __launch_bounds__(256) void k_spec(const float* __restrict__ mass) {
    __shared__ uint32_t sm[STG_U32];
    int b = blockIdx.y;
    int v0 = blockIdx.x * 128;
    float acc[2][8][4]; zacc(acc);
    int n = threadIdx.x & 127;
    int pr = threadIdx.x >> 7;
    const uint32_t* AH = g_evBh + (long)b * 128 * 2048;
    const uint32_t* AL = g_evBl + (long)b * 128 * 2048;
    for (int kt = 0; kt < 4; kt++) {
        __syncthreads();
        uint4 pv[4];
        pfPk(pv, AH, AL, 2048, (long)(v0 >> 1) + kt * 16);
        stPk(sm + AH_OFF, sm + AL_OFF, pv);
        #pragma unroll
        for (int i = 0; i < 8; i++) {
            int p = pr * 8 + i;
            long v = (long)(b * Vv + v0 + kt * 32 + 2 * p);
            float v0f = g_x[v * 128 + n] * mass[v];
            float v1f = g_x[(v + 1) * 128 + n] * mass[v + 1];
            split2(v0f, v1f, sm[BH_OFF + n*KP + p], sm[BL_OFF + n*KP + p]);
        }
        __syncthreads();
        mma_step(sm, 0, acc);
        mma_step(sm, 1, acc);
    }
    int lane = threadIdx.x & 31, g = lane >> 2, t4 = lane & 3;
    int wid = threadIdx.x >> 5;
    int m0 = (wid & 3) * 32, n0 = (wid >> 2) * 64;
    float* outb = g_xspec + b * Kk * Cc;
    #pragma unroll
    for (int mt = 0; mt < 2; mt++)
        #pragma unroll
        for (int nt = 0; nt < 8; nt++) {
            int r = m0 + mt * 16 + g;
            int c = n0 + nt * 8 + t4 * 2;
            atomicAdd(&outb[r * 128 + c],           acc[mt][nt][0]);
            atomicAdd(&outb[r * 128 + c + 1],       acc[mt][nt][1]);
            atomicAdd(&outb[(r + 8) * 128 + c],     acc[mt][nt][2]);
            atomicAdd(&outb[(r + 8) * 128 + c + 1], acc[mt][nt][3]);
        }
}

__global__ __launch_bounds__(256) void k_scale(const float* __restrict__ evals,
                                               const float* __restrict__ tpar, int blk) {
    int gid = blockIdx.x * 256 + threadIdx.x;
    int p = gid & 63;
    int c = (gid >> 6) & 127;
    int b = gid >> 13;
    float ti = fmaxf(tpar[blk * 128 + c], 1e-8f);
    int k0 = 2 * p;
    float v0 = expf(-evals[b * 128 + k0] * ti)     * g_xspec[(b * 128 + k0) * 128 + c];
    float v1 = expf(-evals[b * 128 + k0 + 1] * ti) * g_xspec[(b * 128 + k0 + 1) * 128 + c];
    split2(v0, v1, g_ysh[gid], g_ysl[gid]);
}

// xdiff / gx / gy — pipelined packed copies
__global__ __launch_bounds__(256) void k_fbg() {
    __shared__ uint32_t sm[STG_U32];
    int b = blockIdx.y, z = blockIdx.z;
    int row0 = blockIdx.x * 128;
    long rowg = (long)b * Vv + row0;
    const uint32_t *AH, *AL;
    float* O;
    if (z == 0)      { AH = g_evAh + rowg * 64;  AL = g_evAl + rowg * 64;  O = g_xdiff + (long)b * Vv * Cc; }
    else if (z == 1) { AH = g_gxeAh + rowg * 64; AL = g_gxeAl + rowg * 64; O = g_gx + (long)b * Vv * Cc; }
    else             { AH = g_gyeAh + rowg * 64; AL = g_gyeAl + rowg * 64; O = g_gy + (long)b * Vv * Cc; }
    const uint32_t* BH = g_ysh + (long)b * 128 * 64;
    const uint32_t* BL = g_ysl + (long)b * 128 * 64;
    float acc[2][8][4]; zacc(acc);
    {
        uint4 pa[4], pb_[4];
        pfPk(pa, AH, AL, 64, 0);
        pfPk(pb_, BH, BL, 64, 0);
        stPk(sm + AH_OFF, sm + AL_OFF, pa);
        stPk(sm + BH_OFF, sm + BL_OFF, pb_);
    }
    __syncthreads();
    for (int kt = 0; kt < 4; kt++) {
        uint4 pa[4], pb_[4];
        bool has = (kt < 3);
        if (has) {
            pfPk(pa, AH, AL, 64, (kt + 1) * 16);
            pfPk(pb_, BH, BL, 64, (kt + 1) * 16);
        }
        mma_step(sm, 0, acc);
        mma_step(sm, 1, acc);
        __syncthreads();
        if (has) {
            stPk(sm + AH_OFF, sm + AL_OFF, pa);
            stPk(sm + BH_OFF, sm + BL_OFF, pb_);
        }
        __syncthreads();
    }
    int lane = threadIdx.x & 31, g = lane >> 2, t4 = lane & 3;
    int wid = threadIdx.x >> 5;
    int m0 = (wid & 3) * 32, n0 = (wid >> 2) * 64;
    #pragma unroll
    for (int mt = 0; mt < 2; mt++)
        #pragma unroll
        for (int nt = 0; nt < 8; nt++) {
            int r = row0 + m0 + mt * 16 + g;
            int c = n0 + nt * 8 + t4 * 2;
            *(float2*)(O + (long)r * 128 + c)       = make_float2(acc[mt][nt][0], acc[mt][nt][1]);
            *(float2*)(O + (long)(r + 8) * 128 + c) = make_float2(acc[mt][nt][2], acc[mt][nt][3]);
        }
}

// ---------------- fused complex-linear + tanh ----------------
__global__ __launch_bounds__(256) void k_cplx(const float* __restrict__ Are,
                                              const float* __restrict__ Aim) {
    extern __shared__ uint32_t smc[];
    uint32_t* st0 = smc;
    uint32_t* st1 = smc + STG_U32;
    int b = blockIdx.y;
    long off = (long)b * Vv * Cc;
    int row0 = blockIdx.x * 128;
    int lane = threadIdx.x & 31, g = lane >> 2, t4 = lane & 3;
    int wid = threadIdx.x >> 5;
    int m0 = (wid & 3) * 32, n0 = (wid >> 2) * 64;
    float abr[2][8][4]; zacc(abr);
    float abi[2][8][4]; zacc(abi);
    for (int kt = 0; kt < 4; kt++) {
        __syncthreads();
        {
            float4 av[4]; float bv[16];
            pfA(av, g_gx + off + (long)row0 * Cc, Cc, kt);
            pfB(bv, Are, kt);
            stA(st0 + AH_OFF, st0 + AL_OFF, av);
            stB(st0 + BH_OFF, st0 + BL_OFF, bv);
            pfA(av, g_gy + off + (long)row0 * Cc, Cc, kt);
            pfB(bv, Aim, kt);
            stA(st1 + AH_OFF, st1 + AL_OFF, av);
            stB(st1 + BH_OFF, st1 + BL_OFF, bv);
        }
        __syncthreads();
        #pragma unroll
        for (int ks = 0; ks < 2; ks++) {
            int pb = ks * 8 + t4;
            uint32_t xh[2][4], xl[2][4], yh[2][4], yl[2][4];
            #pragma unroll
            for (int mt = 0; mt < 2; mt++) {
                int m = m0 + mt * 16 + g;
                xh[mt][0] = st0[AH_OFF+m*KP+pb];   xh[mt][1] = st0[AH_OFF+(m+8)*KP+pb];
                xh[mt][2] = st0[AH_OFF+m*KP+pb+4]; xh[mt][3] = st0[AH_OFF+(m+8)*KP+pb+4];
                xl[mt][0] = st0[AL_OFF+m*KP+pb];   xl[mt][1] = st0[AL_OFF+(m+8)*KP+pb];
                xl[mt][2] = st0[AL_OFF+m*KP+pb+4]; xl[mt][3] = st0[AL_OFF+(m+8)*KP+pb+4];
                yh[mt][0] = st1[AH_OFF+m*KP+pb];   yh[mt][1] = st1[AH_OFF+(m+8)*KP+pb];
                yh[mt][2] = st1[AH_OFF+m*KP+pb+4]; yh[mt][3] = st1[AH_OFF+(m+8)*KP+pb+4];
                yl[mt][0] = st1[AL_OFF+m*KP+pb];   yl[mt][1] = st1[AL_OFF+(m+8)*KP+pb];
                yl[mt][2] = st1[AL_OFF+m*KP+pb+4]; yl[mt][3] = st1[AL_OFF+(m+8)*KP+pb+4];
            }
            #pragma unroll
            for (int nt = 0; nt < 8; nt++) {
                int n = n0 + nt * 8 + g;
                uint32_t rh0 = st0[BH_OFF+n*KP+pb], rh1 = st0[BH_OFF+n*KP+pb+4];
                uint32_t rl0 = st0[BL_OFF+n*KP+pb], rl1 = st0[BL_OFF+n*KP+pb+4];
                uint32_t ih0 = st1[BH_OFF+n*KP+pb], ih1 = st1[BH_OFF+n*KP+pb+4];
                uint32_t il0 = st1[BL_OFF+n*KP+pb], il1 = st1[BL_OFF+n*KP+pb+4];
                uint32_t nh0 = ih0 ^ 0x80008000u, nh1 = ih1 ^ 0x80008000u;
                uint32_t nl0 = il0 ^ 0x80008000u, nl1 = il1 ^ 0x80008000u;
                #pragma unroll
                for (int mt = 0; mt < 2; mt++) {
                    MMA_BF16(abr[mt][nt], xh[mt], rh0, rh1);
                    MMA_BF16(abr[mt][nt], xh[mt], rl0, rl1);
                    MMA_BF16(abr[mt][nt], xl[mt], rh0, rh1);
                    MMA_BF16(abr[mt][nt], yh[mt], nh0, nh1);
                    MMA_BF16(abr[mt][nt], yh[mt], nl0, nl1);
                    MMA_BF16(abr[mt][nt], yl[mt], nh0, nh1);
                    MMA_BF16(abi[mt][nt], yh[mt], rh0, rh1);
                    MMA_BF16(abi[mt][nt], yh[mt], rl0, rl1);
                    MMA_BF16(abi[mt][nt], yl[mt], rh0, rh1);
                    MMA_BF16(abi[mt][nt], xh[mt], ih0, ih1);
                    MMA_BF16(abi[mt][nt], xh[mt], il0, il1);
                    MMA_BF16(abi[mt][nt], xl[mt], ih0, ih1);
                }
            }
        }
    }
    #pragma unroll
    for (int mt = 0; mt < 2; mt++)
        #pragma unroll
        for (int nt = 0; nt < 8; nt++) {
            int c = n0 + nt * 8 + t4 * 2;
            #pragma unroll
            for (int h = 0; h < 2; h++) {
                int r = row0 + m0 + mt * 16 + g + h * 8;
                long base = off + (long)r * 128 + c;
                float2 gx2 = *(const float2*)(g_gx + base);
                float2 gy2 = *(const float2*)(g_gy + base);
                float2 o;
                o.x = tanhf(gx2.x * abr[mt][nt][h*2]   + gy2.x * abi[mt][nt][h*2]);
                o.y = tanhf(gx2.y * abr[mt][nt][h*2+1] + gy2.y * abi[mt][nt][h*2+1]);
                *(float2*)(g_gfeat + base) = o;
            }
        }
}

// ---------------- fused 3-layer MLP (double-buffered B in layers 1-2) ----------------
__global__ __launch_bounds__(256) void k_mlp(const float* __restrict__ W0,
                                             const float* __restrict__ b0,
                                             const float* __restrict__ W1,
                                             const float* __restrict__ b1,
                                             const float* __restrict__ W2,
                                             const float* __restrict__ b2) {
    extern __shared__ uint32_t smd[];
    uint32_t* stage = smd;                      // full stage for layer 0
    uint32_t* bst   = smd + BH_OFF;             // B region of stage + extra = 2 B buffers
    uint32_t* hH = smd + STG_U32 + BSTG;
    uint32_t* hL = hH + 128 * HST;
    int row0 = blockIdx.x * 128;
    int lane = threadIdx.x & 31, g = lane >> 2, t4 = lane & 3;
    int wid = threadIdx.x >> 5;
    int m0 = (wid & 3) * 32, n0 = (wid >> 2) * 64;

    float acc[2][8][4]; zacc(acc);
    mma_gemm(stage, g_x     + (long)row0 * Cc, Cc, W0,             Cc, acc);
    mma_gemm(stage, g_xdiff + (long)row0 * Cc, Cc, W0 + 128 * 128, Cc, acc);
    mma_gemm(stage, g_gfeat + (long)row0 * Cc, Cc, W0 + 256 * 128, Cc, acc);

    #pragma unroll
    for (int mt = 0; mt < 2; mt++)
        #pragma unroll
        for (int nt = 0; nt < 8; nt++) {
            int c = n0 + nt * 8 + t4 * 2;
            float2 bb = *(const float2*)(b0 + c);
            int cp = c >> 1;
            int r = m0 + mt * 16 + g;
            split2(fmaxf(acc[mt][nt][0] + bb.x, 0.0f), fmaxf(acc[mt][nt][1] + bb.y, 0.0f),
                   hH[r * HST + cp], hL[r * HST + cp]);
            split2(fmaxf(acc[mt][nt][2] + bb.x, 0.0f), fmaxf(acc[mt][nt][3] + bb.y, 0.0f),
                   hH[(r + 8) * HST + cp], hL[(r + 8) * HST + cp]);
        }
    __syncthreads();

    zacc(acc);
    smemA_gemm2(hH, hL, bst, W1, acc);
    __syncthreads();   // all reads of h0 complete before overwrite
    #pragma unroll
    for (int mt = 0; mt < 2; mt++)
        #pragma unroll
        for (int nt = 0; nt < 8; nt++) {
            int c = n0 + nt * 8 + t4 * 2;
            float2 bb = *(const float2*)(b1 + c);
            int cp = c >> 1;
            int r = m0 + mt * 16 + g;
            split2(fmaxf(acc[mt][nt][0] + bb.x, 0.0f), fmaxf(acc[mt][nt][1] + bb.y, 0.0f),
                   hH[r * HST + cp], hL[r * HST + cp]);
            split2(fmaxf(acc[mt][nt][2] + bb.x, 0.0f), fmaxf(acc[mt][nt][3] + bb.y, 0.0f),
                   hH[(r + 8) * HST + cp], hL[(r + 8) * HST + cp]);
        }
    __syncthreads();

    zacc(acc);
    smemA_gemm2(hH, hL, bst, W2, acc);
    #pragma unroll
    for (int mt = 0; mt < 2; mt++)
        #pragma unroll
        for (int nt = 0; nt < 8; nt++) {
            int c = n0 + nt * 8 + t4 * 2;
            float2 bb = *(const float2*)(b2 + c);
            #pragma unroll
            for (int h = 0; h < 2; h++) {
                int r = row0 + m0 + mt * 16 + g + h * 8;
                float2 xv = *(const float2*)(g_x + (long)r * 128 + c);
                xv.x += acc[mt][nt][h * 2]     + bb.x;
                xv.y += acc[mt][nt][h * 2 + 1] + bb.y;
                *(float2*)(g_x + (long)r * 128 + c) = xv;
            }
        }
}

// ---------------- final linear ----------------
__global__ __launch_bounds__(256) void k_final(const float* __restrict__ Wl,
                                               const float* __restrict__ bl,
                                               float* __restrict__ out) {
    __shared__ uint32_t sm[STG_U32];
    int row0 = blockIdx.x * 128;
    float acc[2][8][4]; zacc(acc);
    mma_gemm(sm, g_x + (long)row0 * Cc, Cc, Wl, Cc, acc);
    int lane = threadIdx.x & 31, g = lane >> 2, t4 = lane & 3;
    int wid = threadIdx.x >> 5;
    int m0 = (wid & 3) * 32, n0 = (wid >> 2) * 64;
    #pragma unroll
    for (int mt = 0; mt < 2; mt++)
        #pragma unroll
        for (int nt = 0; nt < 8; nt++) {
            int c = n0 + nt * 8 + t4 * 2;
            float2 bb = *(const float2*)(bl + c);
            int r = row0 + m0 + mt * 16 + g;
            *(float2*)(out + (long)r * 128 + c) = make_float2(
                acc[mt][nt][0] + bb.x, acc[mt][nt][1] + bb.y);
            *(float2*)(out + (long)(r + 8) * 128 + c) = make_float2(
                acc[mt][nt][2] + bb.x, acc[mt][nt][3] + bb.y);
        }
}

// ---------------- launch ----------------
extern "C" void kernel_launch(void* const* d_in, const int* in_sizes, int n_in,
                              void* d_out, int out_size) {
    const float* x_in  = (const float*)d_in[0];
    const float* mass  = (const float*)d_in[1];
    const float* evals = (const float*)d_in[2];
    const float* evecs = (const float*)d_in[3];
    const float* gradX = (const float*)d_in[4];
    const float* gradY = (const float*)d_in[5];
    const float* Wf    = (const float*)d_in[6];
    const float* bf    = (const float*)d_in[7];
    const float* Wl    = (const float*)d_in[8];
    const float* bl    = (const float*)d_in[9];
    const float* t     = (const float*)d_in[10];
    const float* Are   = (const float*)d_in[11];
    const float* Aim   = (const float*)d_in[12];
    const float* W0    = (const float*)d_in[13];
    const float* b0    = (const float*)d_in[14];
    const float* W1    = (const float*)d_in[15];
    const float* b1    = (const float*)d_in[16];
    const float* W2    = (const float*)d_in[17];
    const float* b2    = (const float*)d_in[18];
    float* out = (float*)d_out;

    static int init_attr = 0;
    if (!init_attr) {
        cudaFuncSetAttribute(k_cplx, cudaFuncAttributeMaxDynamicSharedMemorySize, MC_SMEM);
        cudaFuncSetAttribute(k_mlp,  cudaFuncAttributeMaxDynamicSharedMemorySize, MLP_SMEM);
        init_attr = 1;
    }

    k_input<<<(Bb * Vv * Cc) / 256, 256>>>(x_in, Wf, bf);
    k_packEvA<<<(Bb * Vv * 64) / 256, 256>>>(evecs);
    k_packEvB<<<dim3(1024, Bb), 256>>>(evecs);
    k_bigmm<<<dim3(Vv / 128, Bb, 2), 256>>>(gradX, gradY);

    for (int i = 0; i < NBLK; i++) {
        k_zero_spec<<<(Bb * Kk * Cc) / 256, 256>>>();
        k_spec<<<dim3(Vv / 128, Bb), 256>>>(mass);
        k_scale<<<(Bb * 128 * 64) / 256, 256>>>(evals, t, i);
        k_fbg<<<dim3(Vv / 128, Bb, 3), 256>>>();
        k_cplx<<<dim3(Vv / 128, Bb), 256, MC_SMEM>>>(Are + i * Cc * Cc, Aim + i * Cc * Cc);
        k_mlp<<<(Bb * Vv) / 128, 256, MLP_SMEM>>>(W0 + i * 3 * Cc * Cc, b0 + i * Cc,
                                                  W1 + i * Cc * Cc, b1 + i * Cc,
                                                  W2 + i * Cc * Cc, b2 + i * Cc);
    }

    k_final<<<(Bb * Vv) / 128, 256>>>(Wl, bl, out);
}

// round 17
// speedup vs baseline: 1.1867x; 1.0524x over previous
#include <cuda_runtime.h>
#include <cuda_bf16.h>
#include <math.h>
#include <cstdint>

#define Bb   4
#define Vv   4096
#define Kk   128
#define Cc   128
#define NBLK 4
#define KP   20
#define HST  68

#define AH_OFF 0
#define AL_OFF (128*KP)
#define BH_OFF (2*128*KP)
#define BL_OFF (3*128*KP)
#define STG_U32 (4*128*KP)
#define BSTG    (2*128*KP)
#define TILE_U32 (2*128*HST)
#define MLP_SMEM ((STG_U32 + BSTG + TILE_U32) * 4)
#define MC_SMEM  ((STG_U32 + 2*TILE_U32) * 4)

// ---------------- scratch ----------------
__device__ float g_x[Bb*Vv*Cc];
__device__ float g_gfeat[Bb*Vv*Cc];
__device__ float g_xspec[Bb*Kk*Cc];
__device__ uint32_t g_evAh[Bb*Vv*64],  g_evAl[Bb*Vv*64];
__device__ uint32_t g_evBh[Bb*128*2048], g_evBl[Bb*128*2048];
__device__ uint32_t g_gxeAh[Bb*Vv*64], g_gxeAl[Bb*Vv*64];
__device__ uint32_t g_gyeAh[Bb*Vv*64], g_gyeAl[Bb*Vv*64];
__device__ uint32_t g_ysh[Bb*128*64],  g_ysl[Bb*128*64];

// ---------------- helpers ----------------
__device__ __forceinline__ uint32_t f2bf2(float e0, float e1) {
    uint32_t r;
    asm("cvt.rn.bf16x2.f32 %0, %1, %2;" : "=r"(r) : "f"(e1), "f"(e0));
    return r;
}
__device__ __forceinline__ float bhi(float v) {
    return __bfloat162float(__float2bfloat16(v));
}
__device__ __forceinline__ void split2(float v0, float v1, uint32_t& h, uint32_t& l) {
    float h0 = bhi(v0), h1 = bhi(v1);
    h = f2bf2(h0, h1);
    l = f2bf2(v0 - h0, v1 - h1);
}
__device__ __forceinline__ float2 recon2(uint32_t h, uint32_t l) {
    __nv_bfloat162 hb = *(__nv_bfloat162*)&h;
    __nv_bfloat162 lb = *(__nv_bfloat162*)&l;
    return make_float2(__bfloat162float(hb.x) + __bfloat162float(lb.x),
                       __bfloat162float(hb.y) + __bfloat162float(lb.y));
}

#define MMA_BF16(c, a, b0, b1) \
    asm volatile("mma.sync.aligned.m16n8k16.row.col.f32.bf16.bf16.f32 " \
        "{%0,%1,%2,%3},{%4,%5,%6,%7},{%8,%9},{%0,%1,%2,%3};" \
        : "+f"((c)[0]), "+f"((c)[1]), "+f"((c)[2]), "+f"((c)[3]) \
        : "r"((a)[0]), "r"((a)[1]), "r"((a)[2]), "r"((a)[3]), "r"(b0), "r"(b1))

__device__ __forceinline__ void pfA(float4 av[4], const float* __restrict__ A,
                                    long lda, int kt) {
    int row = threadIdx.x >> 1, kh = (threadIdx.x & 1) * 16;
    const float* ap = A + (long)row * lda + kt * 32 + kh;
    av[0] = *(const float4*)ap;
    av[1] = *(const float4*)(ap + 4);
    av[2] = *(const float4*)(ap + 8);
    av[3] = *(const float4*)(ap + 12);
}
__device__ __forceinline__ void stA(uint32_t* H, uint32_t* L, const float4 av[4]) {
    int row = threadIdx.x >> 1, p0 = (threadIdx.x & 1) * 8;
    uint32_t h[8], l[8];
    #pragma unroll
    for (int q = 0; q < 4; q++) {
        float4 v = av[q];
        float h0 = bhi(v.x), h1 = bhi(v.y), h2 = bhi(v.z), h3 = bhi(v.w);
        h[q*2]   = f2bf2(h0, h1);
        h[q*2+1] = f2bf2(h2, h3);
        l[q*2]   = f2bf2(v.x - h0, v.y - h1);
        l[q*2+1] = f2bf2(v.z - h2, v.w - h3);
    }
    uint4* dh = (uint4*)(H + row * KP + p0);
    dh[0] = make_uint4(h[0], h[1], h[2], h[3]);
    dh[1] = make_uint4(h[4], h[5], h[6], h[7]);
    uint4* dl = (uint4*)(L + row * KP + p0);
    dl[0] = make_uint4(l[0], l[1], l[2], l[3]);
    dl[1] = make_uint4(l[4], l[5], l[6], l[7]);
}
__device__ __forceinline__ void pfB(float bv[16], const float* __restrict__ B, int kt) {
    int n = threadIdx.x & 127, pr = threadIdx.x >> 7;
    #pragma unroll
    for (int i = 0; i < 8; i++) {
        int p = pr * 8 + i;
        bv[2*i]   = B[(long)(kt * 32 + 2 * p) * 128 + n];
        bv[2*i+1] = B[(long)(kt * 32 + 2 * p + 1) * 128 + n];
    }
}
__device__ __forceinline__ void stB(uint32_t* H, uint32_t* L, const float bv[16]) {
    int n = threadIdx.x & 127, pr = threadIdx.x >> 7;
    #pragma unroll
    for (int i = 0; i < 8; i++) {
        int p = pr * 8 + i;
        split2(bv[2*i], bv[2*i+1], H[n*KP + p], L[n*KP + p]);
    }
}
__device__ __forceinline__ void pfPk(uint4 r[4], const uint32_t* __restrict__ GH,
                                     const uint32_t* __restrict__ GL, long ldp, long p0) {
    int row = threadIdx.x >> 1, half = threadIdx.x & 1;
    long off = (long)row * ldp + p0 + half * 8;
    r[0] = *(const uint4*)(GH + off);
    r[1] = *(const uint4*)(GH + off + 4);
    r[2] = *(const uint4*)(GL + off);
    r[3] = *(const uint4*)(GL + off + 4);
}
__device__ __forceinline__ void stPk(uint32_t* H, uint32_t* L, const uint4 r[4]) {
    int row = threadIdx.x >> 1, half = threadIdx.x & 1;
    *(uint4*)(H + row * KP + half * 8)     = r[0];
    *(uint4*)(H + row * KP + half * 8 + 4) = r[1];
    *(uint4*)(L + row * KP + half * 8)     = r[2];
    *(uint4*)(L + row * KP + half * 8 + 4) = r[3];
}

__device__ __forceinline__ void mma_step(const uint32_t* st, int ks, float acc[2][8][4]) {
    int lane = threadIdx.x & 31, g = lane >> 2, t4 = lane & 3;
    int wid = threadIdx.x >> 5;
    int m0 = (wid & 3) * 32, n0 = (wid >> 2) * 64;
    int pb = ks * 8 + t4;
    const uint32_t* AH = st + AH_OFF;
    const uint32_t* AL = st + AL_OFF;
    const uint32_t* BHp = st + BH_OFF;
    const uint32_t* BLp = st + BL_OFF;
    uint32_t ah[2][4], al[2][4];
    #pragma unroll
    for (int mt = 0; mt < 2; mt++) {
        int m = m0 + mt * 16 + g;
        ah[mt][0] = AH[m*KP+pb];     ah[mt][1] = AH[(m+8)*KP+pb];
        ah[mt][2] = AH[m*KP+pb+4];   ah[mt][3] = AH[(m+8)*KP+pb+4];
        al[mt][0] = AL[m*KP+pb];     al[mt][1] = AL[(m+8)*KP+pb];
        al[mt][2] = AL[m*KP+pb+4];   al[mt][3] = AL[(m+8)*KP+pb+4];
    }
    #pragma unroll
    for (int nt = 0; nt < 8; nt++) {
        int n = n0 + nt * 8 + g;
        uint32_t bh0 = BHp[n*KP+pb], bh1 = BHp[n*KP+pb+4];
        uint32_t bl0 = BLp[n*KP+pb], bl1 = BLp[n*KP+pb+4];
        #pragma unroll
        for (int mt = 0; mt < 2; mt++) {
            MMA_BF16(acc[mt][nt], ah[mt], bh0, bh1);
            MMA_BF16(acc[mt][nt], ah[mt], bl0, bl1);
            MMA_BF16(acc[mt][nt], al[mt], bh0, bh1);
        }
    }
}

// A from HST-stride packed tile, B from a 2*128*KP region (offset pb within it)
__device__ __forceinline__ void mma_stepA(const uint32_t* AH, const uint32_t* AL,
                                          int pa0, const uint32_t* BHp, const uint32_t* BLp,
                                          int ks, float acc[2][8][4]) {
    int lane = threadIdx.x & 31, g = lane >> 2, t4 = lane & 3;
    int wid = threadIdx.x >> 5;
    int m0 = (wid & 3) * 32, n0 = (wid >> 2) * 64;
    int pa = pa0 + ks * 8 + t4;
    int pb = ks * 8 + t4;
    uint32_t ah[2][4], al[2][4];
    #pragma unroll
    for (int mt = 0; mt < 2; mt++) {
        int m = m0 + mt * 16 + g;
        ah[mt][0] = AH[m*HST+pa];     ah[mt][1] = AH[(m+8)*HST+pa];
        ah[mt][2] = AH[m*HST+pa+4];   ah[mt][3] = AH[(m+8)*HST+pa+4];
        al[mt][0] = AL[m*HST+pa];     al[mt][1] = AL[(m+8)*HST+pa];
        al[mt][2] = AL[m*HST+pa+4];   al[mt][3] = AL[(m+8)*HST+pa+4];
    }
    #pragma unroll
    for (int nt = 0; nt < 8; nt++) {
        int n = n0 + nt * 8 + g;
        uint32_t bh0 = BHp[n*KP+pb], bh1 = BHp[n*KP+pb+4];
        uint32_t bl0 = BLp[n*KP+pb], bl1 = BLp[n*KP+pb+4];
        #pragma unroll
        for (int mt = 0; mt < 2; mt++) {
            MMA_BF16(acc[mt][nt], ah[mt], bh0, bh1);
            MMA_BF16(acc[mt][nt], ah[mt], bl0, bl1);
            MMA_BF16(acc[mt][nt], al[mt], bh0, bh1);
        }
    }
}

__device__ __forceinline__ void zacc(float acc[2][8][4]) {
    #pragma unroll
    for (int i = 0; i < 2; i++)
        #pragma unroll
        for (int j = 0; j < 8; j++)
            #pragma unroll
            for (int q = 0; q < 4; q++) acc[i][j][q] = 0.0f;
}

// pipelined GEMM: fp32 A + fp32 B (K=128 here always as KT arg)
__device__ void mma_gemm(uint32_t* sm, const float* __restrict__ A, long lda,
                         const float* __restrict__ B, int K, float acc[2][8][4]) {
    int KT = K / 32;
    {
        float4 av[4]; float bv[16];
        pfA(av, A, lda, 0);
        pfB(bv, B, 0);
        stA(sm + AH_OFF, sm + AL_OFF, av);
        stB(sm + BH_OFF, sm + BL_OFF, bv);
    }
    __syncthreads();
    for (int kt = 0; kt < KT; kt++) {
        float4 av[4]; float bv[16];
        bool has = (kt + 1 < KT);
        if (has) { pfA(av, A, lda, kt + 1); pfB(bv, B, kt + 1); }
        mma_step(sm, 0, acc);
        mma_step(sm, 1, acc);
        __syncthreads();
        if (has) {
            stA(sm + AH_OFF, sm + AL_OFF, av);
            stB(sm + BH_OFF, sm + BL_OFF, bv);
        }
        __syncthreads();
    }
}

// packed A + packed B (both 64-pair rows), K=128
__device__ void pk_gemm(uint32_t* sm, const uint32_t* __restrict__ AH_,
                        const uint32_t* __restrict__ AL_,
                        const uint32_t* __restrict__ BH_,
                        const uint32_t* __restrict__ BL_, float acc[2][8][4]) {
    {
        uint4 pa[4], pb_[4];
        pfPk(pa, AH_, AL_, 64, 0);
        pfPk(pb_, BH_, BL_, 64, 0);
        stPk(sm + AH_OFF, sm + AL_OFF, pa);
        stPk(sm + BH_OFF, sm + BL_OFF, pb_);
    }
    __syncthreads();
    for (int kt = 0; kt < 4; kt++) {
        uint4 pa[4], pb_[4];
        bool has = (kt < 3);
        if (has) {
            pfPk(pa, AH_, AL_, 64, (kt + 1) * 16);
            pfPk(pb_, BH_, BL_, 64, (kt + 1) * 16);
        }
        mma_step(sm, 0, acc);
        mma_step(sm, 1, acc);
        __syncthreads();
        if (has) {
            stPk(sm + AH_OFF, sm + AL_OFF, pa);
            stPk(sm + BH_OFF, sm + BL_OFF, pb_);
        }
        __syncthreads();
    }
}

// write acc into packed HST-stride tile
__device__ __forceinline__ void st_tile(float acc[2][8][4], uint32_t* TH, uint32_t* TL) {
    int lane = threadIdx.x & 31, g = lane >> 2, t4 = lane & 3;
    int wid = threadIdx.x >> 5;
    int m0 = (wid & 3) * 32, n0 = (wid >> 2) * 64;
    #pragma unroll
    for (int mt = 0; mt < 2; mt++)
        #pragma unroll
        for (int nt = 0; nt < 8; nt++) {
            int cp = (n0 + nt * 8 + t4 * 2) >> 1;
            int r = m0 + mt * 16 + g;
            split2(acc[mt][nt][0], acc[mt][nt][1], TH[r * HST + cp], TL[r * HST + cp]);
            split2(acc[mt][nt][2], acc[mt][nt][3], TH[(r + 8) * HST + cp], TL[(r + 8) * HST + cp]);
        }
}

// smem-A GEMM with double-buffered B stage (one sync per chunk)
__device__ void smemA_gemm2(const uint32_t* AH, const uint32_t* AL, uint32_t* bst,
                            const float* __restrict__ B, float acc[2][8][4]) {
    {
        float bv[16];
        pfB(bv, B, 0);
        stB(bst, bst + 128 * KP, bv);
    }
    __syncthreads();
    for (int kt = 0; kt < 4; kt++) {
        uint32_t* cur = bst + (kt & 1) * BSTG;
        bool has = (kt < 3);
        if (has) {
            float bv[16];
            pfB(bv, B, kt + 1);
            mma_stepA(AH, AL, kt * 16, cur, cur + 128 * KP, 0, acc);
            mma_stepA(AH, AL, kt * 16, cur, cur + 128 * KP, 1, acc);
            uint32_t* nxt = bst + ((kt + 1) & 1) * BSTG;
            stB(nxt, nxt + 128 * KP, bv);
        } else {
            mma_stepA(AH, AL, kt * 16, cur, cur + 128 * KP, 0, acc);
            mma_stepA(AH, AL, kt * 16, cur, cur + 128 * KP, 1, acc);
        }
        __syncthreads();
    }
}

// ---------------- pack kernels ----------------
__global__ __launch_bounds__(256) void k_packEvA(const float* __restrict__ evecs) {
    int gid = blockIdx.x * 256 + threadIdx.x;
    float2 v = ((const float2*)evecs)[gid];
    split2(v.x, v.y, g_evAh[gid], g_evAl[gid]);
}
__global__ __launch_bounds__(256) void k_packEvB(const float* __restrict__ evecs) {
    int b = blockIdx.y;
    int e = blockIdx.x * 256 + threadIdx.x;
    int p = e & 2047, n = e >> 11;
    const float* src = evecs + (long)b * Vv * 128;
    float v0 = src[(long)(2 * p) * 128 + n];
    float v1 = src[(long)(2 * p + 1) * 128 + n];
    long o = ((long)b * 128 + n) * 2048 + p;
    split2(v0, v1, g_evBh[o], g_evBl[o]);
}
__global__ __launch_bounds__(256) void k_input(const float* __restrict__ xin,
                                               const float* __restrict__ Wf,
                                               const float* __restrict__ bf) {
    int gid = blockIdx.x * 256 + threadIdx.x;
    int r = gid >> 7, c = gid & 127;
    float s = bf[c];
    #pragma unroll
    for (int k = 0; k < 16; k++) s += xin[r * 16 + k] * Wf[k * 128 + c];
    g_x[gid] = s;
}

// ---------------- big GEMM (frozen R7 structure) ----------------
__global__ __launch_bounds__(256) void k_bigmm(const float* __restrict__ gradX,
                                               const float* __restrict__ gradY) {
    __shared__ uint32_t sm[STG_U32];
    int b = blockIdx.y, z = blockIdx.z;
    int row0 = blockIdx.x * 128;
    const float* A = (z ? gradY : gradX) + (long)b * Vv * Vv + (long)row0 * Vv;
    const uint32_t* BH = g_evBh + (long)b * 128 * 2048;
    const uint32_t* BL = g_evBl + (long)b * 128 * 2048;
    float acc[2][8][4]; zacc(acc);
    {
        float4 av[4]; uint4 pv[4];
        pfA(av, A, Vv, 0);
        pfPk(pv, BH, BL, 2048, 0);
        stA(sm + AH_OFF, sm + AL_OFF, av);
        stPk(sm + BH_OFF, sm + BL_OFF, pv);
    }
    __syncthreads();
    for (int kt = 0; kt < 128; kt++) {
        float4 av[4]; uint4 pv[4];
        bool has = (kt < 127);
        if (has) {
            pfA(av, A, Vv, kt + 1);
            pfPk(pv, BH, BL, 2048, (long)(kt + 1) * 16);
        }
        mma_step(sm, 0, acc);
        mma_step(sm, 1, acc);
        __syncthreads();
        if (has) {
            stA(sm + AH_OFF, sm + AL_OFF, av);
            stPk(sm + BH_OFF, sm + BL_OFF, pv);
        }
        __syncthreads();
    }
    uint32_t* DH = (z ? g_gyeAh : g_gxeAh) + (long)b * Vv * 64;
    uint32_t* DL = (z ? g_gyeAl : g_gxeAl) + (long)b * Vv * 64;
    int lane = threadIdx.x & 31, g = lane >> 2, t4 = lane & 3;
    int wid = threadIdx.x >> 5;
    int m0 = (wid & 3) * 32, n0 = (wid >> 2) * 64;
    #pragma unroll
    for (int mt = 0; mt < 2; mt++)
        #pragma unroll
        for (int nt = 0; nt < 8; nt++) {
            int cp = (n0 + nt * 8 + t4 * 2) >> 1;
            long r = row0 + m0 + mt * 16 + g;
            split2(acc[mt][nt][0], acc[mt][nt][1], DH[r * 64 + cp], DL[r * 64 + cp]);
            split2(acc[mt][nt][2], acc[mt][nt][3], DH[(r + 8) * 64 + cp], DL[(r + 8) * 64 + cp]);
        }
}

// ---------------- spectral ----------------
__global__ __launch_bounds__(256) void k_zero_spec() {
    g_xspec[blockIdx.x * 256 + threadIdx.x] = 0.0f;
}

__global__ __launch_bounds__(256) void k_spec(const float* __restrict__ mass) {
    __shared__ uint32_t sm[STG_U32];
    int b = blockIdx.y;
    int v0 = blockIdx.x * 128;
    float acc[2][8][4]; zacc(acc);
    int n = threadIdx.x & 127;
    int pr = threadIdx.x >> 7;
    const uint32_t* AH = g_evBh + (long)b * 128 * 2048;
    const uint32_t* AL = g_evBl + (long)b * 128 * 2048;
    for (int kt = 0; kt < 4; kt++) {
        __syncthreads();
        uint4 pv[4];
        pfPk(pv, AH, AL, 2048, (long)(v0 >> 1) + kt * 16);
        stPk(sm + AH_OFF, sm + AL_OFF, pv);
        #pragma unroll
        for (int i = 0; i < 8; i++) {
            int p = pr * 8 + i;
            long v = (long)(b * Vv + v0 + kt * 32 + 2 * p);
            float v0f = g_x[v * 128 + n] * mass[v];
            float v1f = g_x[(v + 1) * 128 + n] * mass[v + 1];
            split2(v0f, v1f, sm[BH_OFF + n*KP + p], sm[BL_OFF + n*KP + p]);
        }
        __syncthreads();
        mma_step(sm, 0, acc);
        mma_step(sm, 1, acc);
    }
    int lane = threadIdx.x & 31, g = lane >> 2, t4 = lane & 3;
    int wid = threadIdx.x >> 5;
    int m0 = (wid & 3) * 32, n0 = (wid >> 2) * 64;
    float* outb = g_xspec + b * Kk * Cc;
    #pragma unroll
    for (int mt = 0; mt < 2; mt++)
        #pragma unroll
        for (int nt = 0; nt < 8; nt++) {
            int r = m0 + mt * 16 + g;
            int c = n0 + nt * 8 + t4 * 2;
            atomicAdd(&outb[r * 128 + c],           acc[mt][nt][0]);
            atomicAdd(&outb[r * 128 + c + 1],       acc[mt][nt][1]);
            atomicAdd(&outb[(r + 8) * 128 + c],     acc[mt][nt][2]);
            atomicAdd(&outb[(r + 8) * 128 + c + 1], acc[mt][nt][3]);
        }
}

__global__ __launch_bounds__(256) void k_scale(const float* __restrict__ evals,
                                               const float* __restrict__ tpar, int blk) {
    int gid = blockIdx.x * 256 + threadIdx.x;
    int p = gid & 63;
    int c = (gid >> 6) & 127;
    int b = gid >> 13;
    float ti = fmaxf(tpar[blk * 128 + c], 1e-8f);
    int k0 = 2 * p;
    float v0 = expf(-evals[b * 128 + k0] * ti)     * g_xspec[(b * 128 + k0) * 128 + c];
    float v1 = expf(-evals[b * 128 + k0 + 1] * ti) * g_xspec[(b * 128 + k0 + 1) * 128 + c];
    split2(v0, v1, g_ysh[gid], g_ysl[gid]);
}

// ---------------- fused: gx/gy tiles in smem + complex-linear + tanh ----------------
__global__ __launch_bounds__(256) void k_cplx(const float* __restrict__ Are,
                                              const float* __restrict__ Aim) {
    extern __shared__ uint32_t smc[];
    uint32_t* stage = smc;                  // STG_U32
    uint32_t* GxH = smc + STG_U32;
    uint32_t* GxL = GxH + 128 * HST;
    uint32_t* GyH = GxL + 128 * HST;
    uint32_t* GyL = GyH + 128 * HST;
    int b = blockIdx.y;
    int row0 = blockIdx.x * 128;
    long rowg = (long)b * Vv + row0;
    const uint32_t* YH = g_ysh + (long)b * 128 * 64;
    const uint32_t* YL = g_ysl + (long)b * 128 * 64;
    int lane = threadIdx.x & 31, g = lane >> 2, t4 = lane & 3;
    int wid = threadIdx.x >> 5;
    int m0 = (wid & 3) * 32, n0 = (wid >> 2) * 64;

    // phase 1: gx, gy tiles into smem
    {
        float acc[2][8][4]; zacc(acc);
        pk_gemm(stage, g_gxeAh + rowg * 64, g_gxeAl + rowg * 64, YH, YL, acc);
        st_tile(acc, GxH, GxL);
        zacc(acc);
        pk_gemm(stage, g_gyeAh + rowg * 64, g_gyeAl + rowg * 64, YH, YL, acc);
        st_tile(acc, GyH, GyL);
    }
    __syncthreads();

    // phase 2: br/bi GEMMs with A from smem tiles
    float abr[2][8][4]; zacc(abr);
    float abi[2][8][4]; zacc(abi);
    for (int kt = 0; kt < 4; kt++) {
        __syncthreads();
        {
            float bv[16];
            pfB(bv, Are, kt);
            stB(stage + AH_OFF, stage + AL_OFF, bv);   // Are in A region
            pfB(bv, Aim, kt);
            stB(stage + BH_OFF, stage + BL_OFF, bv);   // Aim in B region
        }
        __syncthreads();
        #pragma unroll
        for (int ks = 0; ks < 2; ks++) {
            int pb = ks * 8 + t4;
            int pa = kt * 16 + ks * 8 + t4;
            uint32_t xh[2][4], xl[2][4], yh[2][4], yl[2][4];
            #pragma unroll
            for (int mt = 0; mt < 2; mt++) {
                int m = m0 + mt * 16 + g;
                xh[mt][0] = GxH[m*HST+pa];   xh[mt][1] = GxH[(m+8)*HST+pa];
                xh[mt][2] = GxH[m*HST+pa+4]; xh[mt][3] = GxH[(m+8)*HST+pa+4];
                xl[mt][0] = GxL[m*HST+pa];   xl[mt][1] = GxL[(m+8)*HST+pa];
                xl[mt][2] = GxL[m*HST+pa+4]; xl[mt][3] = GxL[(m+8)*HST+pa+4];
                yh[mt][0] = GyH[m*HST+pa];   yh[mt][1] = GyH[(m+8)*HST+pa];
                yh[mt][2] = GyH[m*HST+pa+4]; yh[mt][3] = GyH[(m+8)*HST+pa+4];
                yl[mt][0] = GyL[m*HST+pa];   yl[mt][1] = GyL[(m+8)*HST+pa];
                yl[mt][2] = GyL[m*HST+pa+4]; yl[mt][3] = GyL[(m+8)*HST+pa+4];
            }
            #pragma unroll
            for (int nt = 0; nt < 8; nt++) {
                int n = n0 + nt * 8 + g;
                uint32_t rh0 = stage[AH_OFF+n*KP+pb], rh1 = stage[AH_OFF+n*KP+pb+4];
                uint32_t rl0 = stage[AL_OFF+n*KP+pb], rl1 = stage[AL_OFF+n*KP+pb+4];
                uint32_t ih0 = stage[BH_OFF+n*KP+pb], ih1 = stage[BH_OFF+n*KP+pb+4];
                uint32_t il0 = stage[BL_OFF+n*KP+pb], il1 = stage[BL_OFF+n*KP+pb+4];
                uint32_t nh0 = ih0 ^ 0x80008000u, nh1 = ih1 ^ 0x80008000u;
                uint32_t nl0 = il0 ^ 0x80008000u, nl1 = il1 ^ 0x80008000u;
                #pragma unroll
                for (int mt = 0; mt < 2; mt++) {
                    MMA_BF16(abr[mt][nt], xh[mt], rh0, rh1);
                    MMA_BF16(abr[mt][nt], xh[mt], rl0, rl1);
                    MMA_BF16(abr[mt][nt], xl[mt], rh0, rh1);
                    MMA_BF16(abr[mt][nt], yh[mt], nh0, nh1);
                    MMA_BF16(abr[mt][nt], yh[mt], nl0, nl1);
                    MMA_BF16(abr[mt][nt], yl[mt], nh0, nh1);
                    MMA_BF16(abi[mt][nt], yh[mt], rh0, rh1);
                    MMA_BF16(abi[mt][nt], yh[mt], rl0, rl1);
                    MMA_BF16(abi[mt][nt], yl[mt], rh0, rh1);
                    MMA_BF16(abi[mt][nt], xh[mt], ih0, ih1);
                    MMA_BF16(abi[mt][nt], xh[mt], il0, il1);
                    MMA_BF16(abi[mt][nt], xl[mt], ih0, ih1);
                }
            }
        }
    }
    // epilogue: gfeat = tanh(gx*br + gy*bi), gx/gy from smem tiles
    float* O = g_gfeat + (long)b * Vv * Cc;
    #pragma unroll
    for (int mt = 0; mt < 2; mt++)
        #pragma unroll
        for (int nt = 0; nt < 8; nt++) {
            int c = n0 + nt * 8 + t4 * 2;
            int cp = c >> 1;
            #pragma unroll
            for (int h = 0; h < 2; h++) {
                int rl_ = m0 + mt * 16 + g + h * 8;
                float2 gx2 = recon2(GxH[rl_ * HST + cp], GxL[rl_ * HST + cp]);
                float2 gy2 = recon2(GyH[rl_ * HST + cp], GyL[rl_ * HST + cp]);
                float2 o;
                o.x = tanhf(gx2.x * abr[mt][nt][h*2]   + gy2.x * abi[mt][nt][h*2]);
                o.y = tanhf(gx2.y * abr[mt][nt][h*2+1] + gy2.y * abi[mt][nt][h*2+1]);
                *(float2*)(O + (long)(row0 + rl_) * 128 + c) = o;
            }
        }
}

// ---------------- fused MLP (+ xdiff tile computed in-kernel) ----------------
__global__ __launch_bounds__(256) void k_mlp(const float* __restrict__ W0,
                                             const float* __restrict__ b0,
                                             const float* __restrict__ W1,
                                             const float* __restrict__ b1,
                                             const float* __restrict__ W2,
                                             const float* __restrict__ b2) {
    extern __shared__ uint32_t smd[];
    uint32_t* stage = smd;
    uint32_t* bst   = smd + BH_OFF;
    uint32_t* hH = smd + STG_U32 + BSTG;
    uint32_t* hL = hH + 128 * HST;
    int row0 = blockIdx.x * 128;
    int b = blockIdx.x >> 5;              // 32 tiles per batch
    long rowg = (long)row0;               // evA is flat-indexed
    const uint32_t* YH = g_ysh + (long)b * 128 * 64;
    const uint32_t* YL = g_ysl + (long)b * 128 * 64;
    int lane = threadIdx.x & 31, g = lane >> 2, t4 = lane & 3;
    int wid = threadIdx.x >> 5;
    int m0 = (wid & 3) * 32, n0 = (wid >> 2) * 64;

    float acc[2][8][4];

    // xdiff tile = evA @ yspec -> h-tile (packed)
    zacc(acc);
    pk_gemm(stage, g_evAh + rowg * 64, g_evAl + rowg * 64, YH, YL, acc);
    st_tile(acc, hH, hL);
    __syncthreads();

    // layer 0: acc = x@W0a + xdiff@W0b + gfeat@W0c
    zacc(acc);
    mma_gemm(stage, g_x + (long)row0 * Cc, Cc, W0, Cc, acc);
    smemA_gemm2(hH, hL, bst, W0 + 128 * 128, acc);
    __syncthreads();
    mma_gemm(stage, g_gfeat + (long)row0 * Cc, Cc, W0 + 256 * 128, Cc, acc);

    #pragma unroll
    for (int mt = 0; mt < 2; mt++)
        #pragma unroll
        for (int nt = 0; nt < 8; nt++) {
            int c = n0 + nt * 8 + t4 * 2;
            float2 bb = *(const float2*)(b0 + c);
            int cp = c >> 1;
            int r = m0 + mt * 16 + g;
            split2(fmaxf(acc[mt][nt][0] + bb.x, 0.0f), fmaxf(acc[mt][nt][1] + bb.y, 0.0f),
                   hH[r * HST + cp], hL[r * HST + cp]);
            split2(fmaxf(acc[mt][nt][2] + bb.x, 0.0f), fmaxf(acc[mt][nt][3] + bb.y, 0.0f),
                   hH[(r + 8) * HST + cp], hL[(r + 8) * HST + cp]);
        }
    __syncthreads();

    zacc(acc);
    smemA_gemm2(hH, hL, bst, W1, acc);
    __syncthreads();
    #pragma unroll
    for (int mt = 0; mt < 2; mt++)
        #pragma unroll
        for (int nt = 0; nt < 8; nt++) {
            int c = n0 + nt * 8 + t4 * 2;
            float2 bb = *(const float2*)(b1 + c);
            int cp = c >> 1;
            int r = m0 + mt * 16 + g;
            split2(fmaxf(acc[mt][nt][0] + bb.x, 0.0f), fmaxf(acc[mt][nt][1] + bb.y, 0.0f),
                   hH[r * HST + cp], hL[r * HST + cp]);
            split2(fmaxf(acc[mt][nt][2] + bb.x, 0.0f), fmaxf(acc[mt][nt][3] + bb.y, 0.0f),
                   hH[(r + 8) * HST + cp], hL[(r + 8) * HST + cp]);
        }
    __syncthreads();

    zacc(acc);
    smemA_gemm2(hH, hL, bst, W2, acc);
    #pragma unroll
    for (int mt = 0; mt < 2; mt++)
        #pragma unroll
        for (int nt = 0; nt < 8; nt++) {
            int c = n0 + nt * 8 + t4 * 2;
            float2 bb = *(const float2*)(b2 + c);
            #pragma unroll
            for (int h = 0; h < 2; h++) {
                int r = row0 + m0 + mt * 16 + g + h * 8;
                float2 xv = *(const float2*)(g_x + (long)r * 128 + c);
                xv.x += acc[mt][nt][h * 2]     + bb.x;
                xv.y += acc[mt][nt][h * 2 + 1] + bb.y;
                *(float2*)(g_x + (long)r * 128 + c) = xv;
            }
        }
}

// ---------------- final linear ----------------
__global__ __launch_bounds__(256) void k_final(const float* __restrict__ Wl,
                                               const float* __restrict__ bl,
                                               float* __restrict__ out) {
    __shared__ uint32_t sm[STG_U32];
    int row0 = blockIdx.x * 128;
    float acc[2][8][4]; zacc(acc);
    mma_gemm(sm, g_x + (long)row0 * Cc, Cc, Wl, Cc, acc);
    int lane = threadIdx.x & 31, g = lane >> 2, t4 = lane & 3;
    int wid = threadIdx.x >> 5;
    int m0 = (wid & 3) * 32, n0 = (wid >> 2) * 64;
    #pragma unroll
    for (int mt = 0; mt < 2; mt++)
        #pragma unroll
        for (int nt = 0; nt < 8; nt++) {
            int c = n0 + nt * 8 + t4 * 2;
            float2 bb = *(const float2*)(bl + c);
            int r = row0 + m0 + mt * 16 + g;
            *(float2*)(out + (long)r * 128 + c) = make_float2(
                acc[mt][nt][0] + bb.x, acc[mt][nt][1] + bb.y);
            *(float2*)(out + (long)(r + 8) * 128 + c) = make_float2(
                acc[mt][nt][2] + bb.x, acc[mt][nt][3] + bb.y);
        }
}

// ---------------- launch ----------------
extern "C" void kernel_launch(void* const* d_in, const int* in_sizes, int n_in,
                              void* d_out, int out_size) {
    const float* x_in  = (const float*)d_in[0];
    const float* mass  = (const float*)d_in[1];
    const float* evals = (const float*)d_in[2];
    const float* evecs = (const float*)d_in[3];
    const float* gradX = (const float*)d_in[4];
    const float* gradY = (const float*)d_in[5];
    const float* Wf    = (const float*)d_in[6];
    const float* bf    = (const float*)d_in[7];
    const float* Wl    = (const float*)d_in[8];
    const float* bl    = (const float*)d_in[9];
    const float* t     = (const float*)d_in[10];
    const float* Are   = (const float*)d_in[11];
    const float* Aim   = (const float*)d_in[12];
    const float* W0    = (const float*)d_in[13];
    const float* b0    = (const float*)d_in[14];
    const float* W1    = (const float*)d_in[15];
    const float* b1    = (const float*)d_in[16];
    const float* W2    = (const float*)d_in[17];
    const float* b2    = (const float*)d_in[18];
    float* out = (float*)d_out;

    static int init_attr = 0;
    if (!init_attr) {
        cudaFuncSetAttribute(k_cplx, cudaFuncAttributeMaxDynamicSharedMemorySize, MC_SMEM);
        cudaFuncSetAttribute(k_mlp,  cudaFuncAttributeMaxDynamicSharedMemorySize, MLP_SMEM);
        init_attr = 1;
    }

    k_input<<<(Bb * Vv * Cc) / 256, 256>>>(x_in, Wf, bf);
    k_packEvA<<<(Bb * Vv * 64) / 256, 256>>>(evecs);
    k_packEvB<<<dim3(1024, Bb), 256>>>(evecs);
    k_bigmm<<<dim3(Vv / 128, Bb, 2), 256>>>(gradX, gradY);

    for (int i = 0; i < NBLK; i++) {
        k_zero_spec<<<(Bb * Kk * Cc) / 256, 256>>>();
        k_spec<<<dim3(Vv / 128, Bb), 256>>>(mass);
        k_scale<<<(Bb * 128 * 64) / 256, 256>>>(evals, t, i);
        k_cplx<<<dim3(Vv / 128, Bb), 256, MC_SMEM>>>(Are + i * Cc * Cc, Aim + i * Cc * Cc);
        k_mlp<<<(Bb * Vv) / 128, 256, MLP_SMEM>>>(W0 + i * 3 * Cc * Cc, b0 + i * Cc,
                                                  W1 + i * Cc * Cc, b1 + i * Cc,
                                                  W2 + i * Cc * Cc, b2 + i * Cc);
    }

    k_final<<<(Bb * Vv) / 128, 256>>>(Wl, bl, out);
}